// round 1
// baseline (speedup 1.0000x reference)
#include <cuda_runtime.h>
#include <math.h>

// Problem constants
#define B_    2
#define T_    64
#define BT_   128
#define CIN_  16
#define HW_   4096
#define OC_   64
#define NH_   8
#define DD_   32768
#define BH_   16

// ---------------- scratch (device globals; no allocation in kernel_launch) ----
__device__ float g_q[(size_t)BH_ * T_ * DD_];     // 128 MB
__device__ float g_k[(size_t)BH_ * T_ * DD_];     // 128 MB
__device__ float g_v[(size_t)BH_ * T_ * DD_];     // 128 MB
__device__ float g_Sp[(size_t)BH_ * 16 * T_ * T_]; // 4 MB partial scores
__device__ float g_att[(size_t)BH_ * T_ * T_];     // 256 KB
__device__ float g_y[(size_t)BT_ * OC_ * HW_];     // 128 MB

// ============================================================================
// Kernel 1: fused QKV 3x3 conv.  x[bt][16][64][64] -> q/k/v in [b,h,t,d] layout
// Tile: 16 rows x 64 cols per block (one image band). 256 threads.
// Per thread: 4 pixels (vertical) x 16 output channels, 12 oc-chunks of 16.
// smem: xs[16][18][66] (halo-padded input) + ws[16][144] + bs[16]
// ============================================================================
__global__ __launch_bounds__(256) void k_qkv(
    const float* __restrict__ x,
    const float* __restrict__ wq, const float* __restrict__ bq,
    const float* __restrict__ wk, const float* __restrict__ bk,
    const float* __restrict__ wv, const float* __restrict__ bv)
{
    extern __shared__ float sm[];
    float* xs = sm;              // 16*18*66 = 19008
    float* ws = sm + 19008;      // 16*144   = 2304
    float* bs = ws + 2304;       // 16

    const int tid   = threadIdx.x;
    const int tiley = blockIdx.x;   // 0..3
    const int bt    = blockIdx.y;   // 0..127

    const float* xin = x + (size_t)bt * CIN_ * HW_;

    // stage input tile with halo (zero pad)
    for (int idx = tid; idx < 16 * 18 * 66; idx += 256) {
        int c = idx / 1188, rem = idx % 1188, r = rem / 66, cc = rem % 66;
        int gy = tiley * 16 + r - 1, gx = cc - 1;
        float v = 0.f;
        if (gy >= 0 && gy < 64 && gx >= 0 && gx < 64) v = xin[c * HW_ + gy * 64 + gx];
        xs[idx] = v;
    }

    const int col = tid & 63;
    const int r0  = (tid >> 6) << 2;      // 0,4,8,12
    const int b   = bt >> 6, t = bt & 63;

    for (int ch = 0; ch < 12; ch++) {
        const int oc0 = ch * 16;            // global oc in [0,192)
        __syncthreads();
        for (int i = tid; i < 2304; i += 256) {
            int o = i / 144, r = i % 144;
            int ocg = oc0 + o;
            const float* wsrc = (ocg < 64) ? wq : ((ocg < 128) ? wk : wv);
            ws[i] = wsrc[(ocg & 63) * 144 + r];
        }
        if (tid < 16) {
            int ocg = oc0 + tid;
            bs[tid] = (ocg < 64) ? bq[ocg] : ((ocg < 128) ? bk[ocg - 64] : bv[ocg - 128]);
        }
        __syncthreads();

        float acc[4][16];
        #pragma unroll
        for (int p = 0; p < 4; p++)
            #pragma unroll
            for (int o = 0; o < 16; o++) acc[p][o] = 0.f;

        for (int c = 0; c < 16; c++) {
            #pragma unroll
            for (int k9 = 0; k9 < 9; k9++) {
                const int kh = k9 / 3, kw = k9 % 3;
                float xv[4];
                #pragma unroll
                for (int p = 0; p < 4; p++) xv[p] = xs[c * 1188 + (r0 + p + kh) * 66 + col + kw];
                #pragma unroll
                for (int o = 0; o < 16; o++) {
                    const float wvv = ws[o * 144 + c * 9 + k9];   // warp broadcast
                    #pragma unroll
                    for (int p = 0; p < 4; p++) acc[p][o] = fmaf(xv[p], wvv, acc[p][o]);
                }
            }
        }

        #pragma unroll
        for (int o = 0; o < 16; o++) {
            const int ocg = oc0 + o;
            float* dst = (ocg < 64) ? g_q : ((ocg < 128) ? g_k : g_v);
            const int ol = ocg & 63;
            const int h = ol >> 3, hc = ol & 7;
            const float bias = bs[o];
            const size_t base = ((size_t)((b * NH_ + h) * T_ + t)) * DD_ + (size_t)hc * HW_;
            #pragma unroll
            for (int p = 0; p < 4; p++) {
                const int row = tiley * 16 + r0 + p;
                dst[base + row * 64 + col] = acc[p][o] + bias;
            }
        }
    }
}

// ============================================================================
// Kernel 2: partial scores Sp[bh][chunk][64][64] over d-chunk of 2048.
// grid (16 chunks, 16 bh), 256 threads, thread = 4x4 of the 64x64 tile.
// Both q and k staged transposed [kk][64] with row stride 68 (conflict-free
// vectorized reads; 4-way write conflicts on staging only).
// ============================================================================
__global__ __launch_bounds__(256) void k_scores()
{
    extern __shared__ float sm[];
    float* qs = sm;          // 128 * 68 = 8704
    float* ks = sm + 8704;   // 8704

    const int tid   = threadIdx.x;
    const int chunk = blockIdx.x;   // 0..15
    const int bh    = blockIdx.y;   // 0..15
    const int i = tid >> 4, j = tid & 15;

    float acc[4][4];
    #pragma unroll
    for (int p = 0; p < 4; p++)
        #pragma unroll
        for (int q = 0; q < 4; q++) acc[p][q] = 0.f;

    for (int sub = 0; sub < 16; sub++) {
        const int d0 = chunk * 2048 + sub * 128;
        __syncthreads();
        for (int idx = tid; idx < 8192; idx += 256) {
            const int row = idx >> 7, dd = idx & 127;
            const size_t g = ((size_t)(bh * T_ + row)) * DD_ + d0 + dd;
            qs[dd * 68 + row] = g_q[g];
            ks[dd * 68 + row] = g_k[g];
        }
        __syncthreads();
        #pragma unroll 4
        for (int kk = 0; kk < 128; kk++) {
            const float4 qv = *(const float4*)&qs[kk * 68 + 4 * i];
            const float4 kv = *(const float4*)&ks[kk * 68 + 4 * j];
            acc[0][0] = fmaf(qv.x, kv.x, acc[0][0]); acc[0][1] = fmaf(qv.x, kv.y, acc[0][1]);
            acc[0][2] = fmaf(qv.x, kv.z, acc[0][2]); acc[0][3] = fmaf(qv.x, kv.w, acc[0][3]);
            acc[1][0] = fmaf(qv.y, kv.x, acc[1][0]); acc[1][1] = fmaf(qv.y, kv.y, acc[1][1]);
            acc[1][2] = fmaf(qv.y, kv.z, acc[1][2]); acc[1][3] = fmaf(qv.y, kv.w, acc[1][3]);
            acc[2][0] = fmaf(qv.z, kv.x, acc[2][0]); acc[2][1] = fmaf(qv.z, kv.y, acc[2][1]);
            acc[2][2] = fmaf(qv.z, kv.z, acc[2][2]); acc[2][3] = fmaf(qv.z, kv.w, acc[2][3]);
            acc[3][0] = fmaf(qv.w, kv.x, acc[3][0]); acc[3][1] = fmaf(qv.w, kv.y, acc[3][1]);
            acc[3][2] = fmaf(qv.w, kv.z, acc[3][2]); acc[3][3] = fmaf(qv.w, kv.w, acc[3][3]);
        }
    }
    #pragma unroll
    for (int p = 0; p < 4; p++)
        #pragma unroll
        for (int q = 0; q < 4; q++)
            g_Sp[((size_t)(bh * 16 + chunk) * T_ + (4 * i + p)) * T_ + 4 * j + q] = acc[p][q];
}

// ============================================================================
// Kernel 3: reduce partials + causal softmax. grid (64 t, 16 bh), 64 threads.
// ============================================================================
__global__ void k_softmax()
{
    const int t = blockIdx.x, bh = blockIdx.y, k = threadIdx.x;
    __shared__ float red[64];
    float s = 0.f;
    #pragma unroll
    for (int ch = 0; ch < 16; ch++)
        s += g_Sp[((size_t)(bh * 16 + ch) * T_ + t) * T_ + k];
    s *= 0.005524271728019903f;   // 1/sqrt(32768)
    const bool valid = (k <= t);
    red[k] = valid ? s : -3.0e38f;
    __syncthreads();
    for (int off = 32; off; off >>= 1) {
        if (k < off) red[k] = fmaxf(red[k], red[k + off]);
        __syncthreads();
    }
    const float m = red[0];
    __syncthreads();
    const float e = valid ? expf(s - m) : 0.f;
    red[k] = e;
    __syncthreads();
    for (int off = 32; off; off >>= 1) {
        if (k < off) red[k] += red[k + off];
        __syncthreads();
    }
    g_att[((size_t)bh * T_ + t) * T_ + k] = e / red[0];
}

// ============================================================================
// Kernel 4: y = att * V, written in conv layout g_y[bt][oc][px].
// grid (256 d-tiles of 128, 16 bh), 256 threads, thread = 4t x 8d.
// ============================================================================
__global__ __launch_bounds__(256) void k_av()
{
    extern __shared__ float sm[];
    float* as = sm;          // 64*64 = 4096
    float* vs = sm + 4096;   // 64*128 = 8192

    const int tid = threadIdx.x;
    const int dt  = blockIdx.x;     // 0..255
    const int bh  = blockIdx.y;     // 0..15
    const int d0  = dt * 128;

    for (int idx = tid; idx < 4096; idx += 256) as[idx] = g_att[(size_t)bh * 4096 + idx];
    for (int idx = tid; idx < 8192; idx += 256) {
        const int k = idx >> 7, dd = idx & 127;
        vs[idx] = g_v[((size_t)(bh * T_ + k)) * DD_ + d0 + dd];
    }
    __syncthreads();

    const int i = tid >> 4, j = tid & 15;
    float acc[4][8];
    #pragma unroll
    for (int p = 0; p < 4; p++)
        #pragma unroll
        for (int q = 0; q < 8; q++) acc[p][q] = 0.f;

    #pragma unroll 2
    for (int k = 0; k < 64; k++) {
        float a[4];
        #pragma unroll
        for (int p = 0; p < 4; p++) a[p] = as[(4 * i + p) * 64 + k];
        const float4 v0 = *(const float4*)&vs[k * 128 + 8 * j];
        const float4 v1 = *(const float4*)&vs[k * 128 + 8 * j + 4];
        #pragma unroll
        for (int p = 0; p < 4; p++) {
            acc[p][0] = fmaf(a[p], v0.x, acc[p][0]); acc[p][1] = fmaf(a[p], v0.y, acc[p][1]);
            acc[p][2] = fmaf(a[p], v0.z, acc[p][2]); acc[p][3] = fmaf(a[p], v0.w, acc[p][3]);
            acc[p][4] = fmaf(a[p], v1.x, acc[p][4]); acc[p][5] = fmaf(a[p], v1.y, acc[p][5]);
            acc[p][6] = fmaf(a[p], v1.z, acc[p][6]); acc[p][7] = fmaf(a[p], v1.w, acc[p][7]);
        }
    }

    const int h = bh & 7, b = bh >> 3;
    const int hc  = d0 >> 12;        // whole tile in one hc (128 | 4096)
    const int px0 = d0 & 4095;
    const int oc  = h * 8 + hc;
    #pragma unroll
    for (int p = 0; p < 4; p++) {
        const int t  = 4 * i + p;
        const int bt = b * 64 + t;
        float* dst = &g_y[((size_t)(bt * 64 + oc)) * 4096 + px0 + 8 * j];
        float4 o0 = make_float4(acc[p][0], acc[p][1], acc[p][2], acc[p][3]);
        float4 o1 = make_float4(acc[p][4], acc[p][5], acc[p][6], acc[p][7]);
        *(float4*)(dst)     = o0;
        *(float4*)(dst + 4) = o1;
    }
}

// ============================================================================
// Kernel 5: output 3x3 conv (C=64 -> OC=64) over g_y, writes d_out.
// Same tiling as k1; c-chunks of 16 (4 passes), oc-chunks of 16.
// ============================================================================
__global__ __launch_bounds__(256) void k_convo(
    const float* __restrict__ wo, const float* __restrict__ bo, float* __restrict__ out)
{
    extern __shared__ float sm[];
    float* xs = sm;              // 19008
    float* ws = sm + 19008;      // 16oc * 16c * 9 = 2304

    const int tid   = threadIdx.x;
    const int tiley = blockIdx.x;
    const int bt    = blockIdx.y;
    const int col   = tid & 63;
    const int r0    = (tid >> 6) << 2;
    const float* yin = g_y + (size_t)bt * OC_ * HW_;

    for (int occ = 0; occ < 4; occ++) {
        const int oc0 = occ * 16;
        float acc[4][16];
        #pragma unroll
        for (int p = 0; p < 4; p++)
            #pragma unroll
            for (int o = 0; o < 16; o++) acc[p][o] = 0.f;

        for (int ccl = 0; ccl < 4; ccl++) {
            const int c0 = ccl * 16;
            __syncthreads();
            for (int idx = tid; idx < 19008; idx += 256) {
                int c = idx / 1188, rem = idx % 1188, r = rem / 66, cc = rem % 66;
                int gy = tiley * 16 + r - 1, gx = cc - 1;
                float v = 0.f;
                if (gy >= 0 && gy < 64 && gx >= 0 && gx < 64) v = yin[(c0 + c) * HW_ + gy * 64 + gx];
                xs[idx] = v;
            }
            for (int idx2 = tid; idx2 < 2304; idx2 += 256) {
                int o = idx2 / 144, r = idx2 % 144;
                int c = r / 9, k9 = r % 9;
                ws[idx2] = wo[((size_t)(oc0 + o) * 64 + c0 + c) * 9 + k9];
            }
            __syncthreads();

            for (int c = 0; c < 16; c++) {
                #pragma unroll
                for (int k9 = 0; k9 < 9; k9++) {
                    const int kh = k9 / 3, kw = k9 % 3;
                    float xv[4];
                    #pragma unroll
                    for (int p = 0; p < 4; p++) xv[p] = xs[c * 1188 + (r0 + p + kh) * 66 + col + kw];
                    #pragma unroll
                    for (int o = 0; o < 16; o++) {
                        const float wvv = ws[o * 144 + c * 9 + k9];
                        #pragma unroll
                        for (int p = 0; p < 4; p++) acc[p][o] = fmaf(xv[p], wvv, acc[p][o]);
                    }
                }
            }
        }

        #pragma unroll
        for (int o = 0; o < 16; o++) {
            const float bias = __ldg(&bo[oc0 + o]);
            #pragma unroll
            for (int p = 0; p < 4; p++) {
                const int row = tiley * 16 + r0 + p;
                out[((size_t)(bt * 64 + oc0 + o)) * 4096 + row * 64 + col] = acc[p][o] + bias;
            }
        }
    }
}

// ============================================================================
extern "C" void kernel_launch(void* const* d_in, const int* in_sizes, int n_in,
                              void* d_out, int out_size)
{
    const float* x  = (const float*)d_in[0];
    const float* wq = (const float*)d_in[1];
    const float* bq = (const float*)d_in[2];
    const float* wk = (const float*)d_in[3];
    const float* bk = (const float*)d_in[4];
    const float* wv = (const float*)d_in[5];
    const float* bv = (const float*)d_in[6];
    const float* wo = (const float*)d_in[7];
    const float* bo = (const float*)d_in[8];
    float* out = (float*)d_out;

    const int SM1 = (19008 + 2304 + 16) * 4;   // 85312
    const int SM2 = (8704 + 8704) * 4;         // 69632
    const int SM4 = (4096 + 8192) * 4;         // 49152
    const int SM5 = (19008 + 2304) * 4;        // 85248

    cudaFuncSetAttribute(k_qkv,   cudaFuncAttributeMaxDynamicSharedMemorySize, SM1);
    cudaFuncSetAttribute(k_scores,cudaFuncAttributeMaxDynamicSharedMemorySize, SM2);
    cudaFuncSetAttribute(k_av,    cudaFuncAttributeMaxDynamicSharedMemorySize, SM4);
    cudaFuncSetAttribute(k_convo, cudaFuncAttributeMaxDynamicSharedMemorySize, SM5);

    k_qkv   <<<dim3(4, 128), 256, SM1>>>(x, wq, bq, wk, bk, wv, bv);
    k_scores<<<dim3(16, 16), 256, SM2>>>();
    k_softmax<<<dim3(64, 16), 64>>>();
    k_av    <<<dim3(256, 16), 256, SM4>>>();
    k_convo <<<dim3(4, 128), 256, SM5>>>(wo, bo, out);
}

// round 3
// speedup vs baseline: 1.8085x; 1.8085x over previous
#include <cuda_runtime.h>
#include <math.h>

// Problem constants
#define B_    2
#define T_    64
#define BT_   128
#define CIN_  16
#define HW_   4096
#define OC_   64
#define NH_   8
#define DD_   32768
#define BH_   16

// ---------------- scratch (device globals) -----------------------------------
__device__ float g_q[(size_t)BH_ * T_ * DD_];       // 128 MB
__device__ float g_k[(size_t)BH_ * T_ * DD_];       // 128 MB
__device__ float g_v[(size_t)BH_ * T_ * DD_];       // 128 MB
__device__ float g_Sp[(size_t)BH_ * 64 * T_ * T_];  // 16.8 MB partial scores
__device__ float g_att[(size_t)BH_ * T_ * T_];      // 256 KB
__device__ float g_y[(size_t)BT_ * OC_ * HW_];      // 128 MB

// tf32 round: destination must be a b32 register per PTX ISA
__device__ __forceinline__ unsigned to_tf32(float x) {
    unsigned r;
    asm("cvt.rna.tf32.f32 %0, %1;" : "=r"(r) : "f"(x));
    return r;
}
__device__ __forceinline__ float to_tf32f(float x) {
    return __uint_as_float(to_tf32(x));
}

__device__ __forceinline__ void mma_tf32(float& d0, float& d1, float& d2, float& d3,
                                         unsigned a0, unsigned a1, unsigned a2, unsigned a3,
                                         unsigned b0, unsigned b1) {
    asm volatile(
        "mma.sync.aligned.m16n8k8.row.col.f32.tf32.tf32.f32 "
        "{%0,%1,%2,%3},{%4,%5,%6,%7},{%8,%9},{%0,%1,%2,%3};"
        : "+f"(d0), "+f"(d1), "+f"(d2), "+f"(d3)
        : "r"(a0), "r"(a1), "r"(a2), "r"(a3), "r"(b0), "r"(b1));
}

// ============================================================================
// Kernel 1: fused QKV 3x3 conv via TF32 tensor cores (implicit GEMM).
// Block: 2 image rows (128 px) x 192 oc. 256 threads = 8 warps:
//   wm = warp&1 (image row), wn = warp>>1 (oc group of 48).
// Warp tile: M=64 (x coord), N=48, K=144.
// smem: ws[144][200] weights (tf32), xs[16c][4rows][66] halo tile (tf32),
//       bs[192] bias. ws stride 200 -> conflict-free B-frag loads.
// ============================================================================
__global__ __launch_bounds__(256) void k_qkv_tc(
    const float* __restrict__ x,
    const float* __restrict__ wq, const float* __restrict__ bq,
    const float* __restrict__ wk, const float* __restrict__ bk,
    const float* __restrict__ wv, const float* __restrict__ bv)
{
    extern __shared__ float sm[];
    float* ws = sm;                  // 144*200 = 28800
    float* xs = sm + 28800;          // 16*4*66 = 4224
    float* bs = xs + 4224;           // 192

    const int tid = threadIdx.x;
    const int y0  = blockIdx.x * 2;      // 0..62
    const int bt  = blockIdx.y;          // 0..127
    const float* xin = x + (size_t)bt * CIN_ * HW_;

    // stage weights: ws[k][oc] (stride 200), tf32
    for (int idx = tid; idx < 192 * 144; idx += 256) {
        const int oc = idx / 144, k = idx % 144;
        const float* wsrc = (oc < 64) ? wq : ((oc < 128) ? wk : wv);
        ws[k * 200 + oc] = to_tf32f(wsrc[(oc & 63) * 144 + k]);
    }
    if (tid < 192) bs[tid] = (tid < 64) ? bq[tid] : ((tid < 128) ? bk[tid - 64] : bv[tid - 128]);

    // stage x tile rows y0-1 .. y0+2 with halo, tf32
    for (int idx = tid; idx < 16 * 4 * 66; idx += 256) {
        const int c = idx / 264, rem = idx % 264, r = rem / 66, cc = rem % 66;
        const int gy = y0 - 1 + r, gx = cc - 1;
        float v = 0.f;
        if (gy >= 0 && gy < 64 && gx >= 0 && gx < 64) v = xin[c * HW_ + gy * 64 + gx];
        xs[idx] = to_tf32f(v);
    }
    __syncthreads();

    const int warp = tid >> 5, lane = tid & 31;
    const int wm = warp & 1, wn = warp >> 1;
    const int lg = lane >> 2, lt = lane & 3;     // groupID, threadInGroup

    float acc[4][6][4];
    #pragma unroll
    for (int m = 0; m < 4; m++)
        #pragma unroll
        for (int n = 0; n < 6; n++)
            #pragma unroll
            for (int r = 0; r < 4; r++) acc[m][n][r] = 0.f;

    for (int kc = 0; kc < 18; kc++) {
        const int k1 = kc * 8 + lt;
        const int k2 = k1 + 4;
        const int c1 = k1 / 9, r1 = k1 % 9, kh1 = r1 / 3, kw1 = r1 % 3;
        const int c2 = k2 / 9, r2 = k2 % 9, kh2 = r2 / 3, kw2 = r2 % 3;
        const int aA1 = c1 * 264 + (wm + kh1) * 66 + kw1 + lg;
        const int aA2 = c2 * 264 + (wm + kh2) * 66 + kw2 + lg;

        unsigned bfr[6][2];
        #pragma unroll
        for (int n = 0; n < 6; n++) {
            const int oc = wn * 48 + n * 8 + lg;
            bfr[n][0] = __float_as_uint(ws[k1 * 200 + oc]);
            bfr[n][1] = __float_as_uint(ws[k2 * 200 + oc]);
        }
        #pragma unroll
        for (int m = 0; m < 4; m++) {
            const int xo = m * 16;
            const unsigned a0 = __float_as_uint(xs[aA1 + xo]);
            const unsigned a1 = __float_as_uint(xs[aA1 + xo + 8]);
            const unsigned a2 = __float_as_uint(xs[aA2 + xo]);
            const unsigned a3 = __float_as_uint(xs[aA2 + xo + 8]);
            #pragma unroll
            for (int n = 0; n < 6; n++)
                mma_tf32(acc[m][n][0], acc[m][n][1], acc[m][n][2], acc[m][n][3],
                         a0, a1, a2, a3, bfr[n][0], bfr[n][1]);
        }
    }

    // epilogue: scattered stores into q/k/v [b,h,t,hc,y,x]
    const int b = bt >> 6, t = bt & 63, y = y0 + wm;
    #pragma unroll
    for (int m = 0; m < 4; m++) {
        #pragma unroll
        for (int n = 0; n < 6; n++) {
            const int ocA = wn * 48 + n * 8 + 2 * lt;
            const int x0 = m * 16 + lg;
            #pragma unroll
            for (int r = 0; r < 4; r++) {
                const int oc = ocA + (r & 1);
                const int xx = x0 + ((r & 2) ? 8 : 0);
                float* dst = (oc < 64) ? g_q : ((oc < 128) ? g_k : g_v);
                const int ol = oc & 63;
                const size_t addr = ((size_t)((b * 8 + (ol >> 3)) * 64 + t)) * DD_
                                  + (size_t)(ol & 7) * 4096 + y * 64 + xx;
                dst[addr] = acc[m][n][r] + bs[oc];
            }
        }
    }
}

// ============================================================================
// Kernel 2: partial scores Sp[bh][chunk64][64][64] over d-chunk of 512.
// grid (64 chunks, 16 bh), 256 threads, thread = 4x4 of the 64x64 tile.
// ============================================================================
__global__ __launch_bounds__(256) void k_scores()
{
    extern __shared__ float sm[];
    float* qs = sm;          // 128 * 68 = 8704
    float* ks = sm + 8704;

    const int tid   = threadIdx.x;
    const int chunk = blockIdx.x;   // 0..63
    const int bh    = blockIdx.y;
    const int i = tid >> 4, j = tid & 15;

    float acc[4][4];
    #pragma unroll
    for (int p = 0; p < 4; p++)
        #pragma unroll
        for (int q = 0; q < 4; q++) acc[p][q] = 0.f;

    for (int sub = 0; sub < 4; sub++) {
        const int d0 = chunk * 512 + sub * 128;
        __syncthreads();
        for (int idx = tid; idx < 8192; idx += 256) {
            const int row = idx >> 7, dd = idx & 127;
            const size_t g = ((size_t)(bh * T_ + row)) * DD_ + d0 + dd;
            qs[dd * 68 + row] = g_q[g];
            ks[dd * 68 + row] = g_k[g];
        }
        __syncthreads();
        #pragma unroll 4
        for (int kk = 0; kk < 128; kk++) {
            const float4 qv = *(const float4*)&qs[kk * 68 + 4 * i];
            const float4 kv = *(const float4*)&ks[kk * 68 + 4 * j];
            acc[0][0] = fmaf(qv.x, kv.x, acc[0][0]); acc[0][1] = fmaf(qv.x, kv.y, acc[0][1]);
            acc[0][2] = fmaf(qv.x, kv.z, acc[0][2]); acc[0][3] = fmaf(qv.x, kv.w, acc[0][3]);
            acc[1][0] = fmaf(qv.y, kv.x, acc[1][0]); acc[1][1] = fmaf(qv.y, kv.y, acc[1][1]);
            acc[1][2] = fmaf(qv.y, kv.z, acc[1][2]); acc[1][3] = fmaf(qv.y, kv.w, acc[1][3]);
            acc[2][0] = fmaf(qv.z, kv.x, acc[2][0]); acc[2][1] = fmaf(qv.z, kv.y, acc[2][1]);
            acc[2][2] = fmaf(qv.z, kv.z, acc[2][2]); acc[2][3] = fmaf(qv.z, kv.w, acc[2][3]);
            acc[3][0] = fmaf(qv.w, kv.x, acc[3][0]); acc[3][1] = fmaf(qv.w, kv.y, acc[3][1]);
            acc[3][2] = fmaf(qv.w, kv.z, acc[3][2]); acc[3][3] = fmaf(qv.w, kv.w, acc[3][3]);
        }
    }
    #pragma unroll
    for (int p = 0; p < 4; p++)
        #pragma unroll
        for (int q = 0; q < 4; q++)
            g_Sp[((size_t)(bh * 64 + chunk) * T_ + (4 * i + p)) * T_ + 4 * j + q] = acc[p][q];
}

// ============================================================================
// Kernel 3: reduce 64 partials + causal softmax. grid (64 t, 16 bh), 64 thr.
// ============================================================================
__global__ void k_softmax()
{
    const int t = blockIdx.x, bh = blockIdx.y, k = threadIdx.x;
    __shared__ float red[64];
    float s = 0.f;
    #pragma unroll 8
    for (int ch = 0; ch < 64; ch++)
        s += g_Sp[((size_t)(bh * 64 + ch) * T_ + t) * T_ + k];
    s *= 0.005524271728019903f;   // 1/sqrt(32768)
    const bool valid = (k <= t);
    red[k] = valid ? s : -3.0e38f;
    __syncthreads();
    for (int off = 32; off; off >>= 1) {
        if (k < off) red[k] = fmaxf(red[k], red[k + off]);
        __syncthreads();
    }
    const float m = red[0];
    __syncthreads();
    const float e = valid ? expf(s - m) : 0.f;
    red[k] = e;
    __syncthreads();
    for (int off = 32; off; off >>= 1) {
        if (k < off) red[k] += red[k + off];
        __syncthreads();
    }
    g_att[((size_t)bh * T_ + t) * T_ + k] = e / red[0];
}

// ============================================================================
// Kernel 4: y = att * V -> conv layout g_y[bt][oc][px].
// grid (256 d-tiles of 128, 16 bh), 256 threads, thread = 4t x 8d.
// ============================================================================
__global__ __launch_bounds__(256) void k_av()
{
    extern __shared__ float sm[];
    float* as = sm;          // 4096
    float* vs = sm + 4096;   // 8192

    const int tid = threadIdx.x;
    const int dt  = blockIdx.x;
    const int bh  = blockIdx.y;
    const int d0  = dt * 128;

    for (int idx = tid; idx < 4096; idx += 256) as[idx] = g_att[(size_t)bh * 4096 + idx];
    for (int idx = tid; idx < 8192; idx += 256) {
        const int k = idx >> 7, dd = idx & 127;
        vs[idx] = g_v[((size_t)(bh * T_ + k)) * DD_ + d0 + dd];
    }
    __syncthreads();

    const int i = tid >> 4, j = tid & 15;
    float acc[4][8];
    #pragma unroll
    for (int p = 0; p < 4; p++)
        #pragma unroll
        for (int q = 0; q < 8; q++) acc[p][q] = 0.f;

    #pragma unroll 2
    for (int k = 0; k < 64; k++) {
        float a[4];
        #pragma unroll
        for (int p = 0; p < 4; p++) a[p] = as[(4 * i + p) * 64 + k];
        const float4 v0 = *(const float4*)&vs[k * 128 + 8 * j];
        const float4 v1 = *(const float4*)&vs[k * 128 + 8 * j + 4];
        #pragma unroll
        for (int p = 0; p < 4; p++) {
            acc[p][0] = fmaf(a[p], v0.x, acc[p][0]); acc[p][1] = fmaf(a[p], v0.y, acc[p][1]);
            acc[p][2] = fmaf(a[p], v0.z, acc[p][2]); acc[p][3] = fmaf(a[p], v0.w, acc[p][3]);
            acc[p][4] = fmaf(a[p], v1.x, acc[p][4]); acc[p][5] = fmaf(a[p], v1.y, acc[p][5]);
            acc[p][6] = fmaf(a[p], v1.z, acc[p][6]); acc[p][7] = fmaf(a[p], v1.w, acc[p][7]);
        }
    }

    const int h = bh & 7, b = bh >> 3;
    const int hc  = d0 >> 12;
    const int px0 = d0 & 4095;
    const int oc  = h * 8 + hc;
    #pragma unroll
    for (int p = 0; p < 4; p++) {
        const int t  = 4 * i + p;
        const int bt = b * 64 + t;
        float* dst = &g_y[((size_t)(bt * 64 + oc)) * 4096 + px0 + 8 * j];
        *(float4*)(dst)     = make_float4(acc[p][0], acc[p][1], acc[p][2], acc[p][3]);
        *(float4*)(dst + 4) = make_float4(acc[p][4], acc[p][5], acc[p][6], acc[p][7]);
    }
}

// ============================================================================
// Kernel 5: output 3x3 conv (64 -> 64) via TF32 tensor cores.
// Block: 4 image rows (256 px) x 64 oc. 8 warps: wm = warp&3 (row),
// wn = warp>>2 (oc group of 32). Warp tile M=64, N=32.
// K=576, processed as 4 c-chunks of 16c (144 K each).
// smem: ws[144][72] (tf32), xs[16c][6rows][66] (tf32), bias[64].
// ============================================================================
__global__ __launch_bounds__(256) void k_convo_tc(
    const float* __restrict__ wo, const float* __restrict__ bo, float* __restrict__ out)
{
    extern __shared__ float sm[];
    float* ws = sm;                  // 144*72 = 10368
    float* xs = sm + 10368;          // 16*6*66 = 6336
    float* bs = xs + 6336;           // 64

    const int tid = threadIdx.x;
    const int y0  = blockIdx.x * 4;      // 0..60
    const int bt  = blockIdx.y;
    const float* yin = g_y + (size_t)bt * OC_ * HW_;

    if (tid < 64) bs[tid] = bo[tid];

    const int warp = tid >> 5, lane = tid & 31;
    const int wm = warp & 3, wn = warp >> 2;
    const int lg = lane >> 2, lt = lane & 3;

    float acc[4][4][4];
    #pragma unroll
    for (int m = 0; m < 4; m++)
        #pragma unroll
        for (int n = 0; n < 4; n++)
            #pragma unroll
            for (int r = 0; r < 4; r++) acc[m][n][r] = 0.f;

    for (int cc = 0; cc < 4; cc++) {
        __syncthreads();
        // stage weights chunk: ws[kl][oc], kl = 0..143 maps to global k = cc*144+kl
        for (int idx = tid; idx < 64 * 144; idx += 256) {
            const int oc = idx / 144, kl = idx % 144;
            ws[kl * 72 + oc] = to_tf32f(wo[(size_t)oc * 576 + cc * 144 + kl]);
        }
        // stage x chunk: 16 channels (cc*16..), 6 halo rows
        for (int idx = tid; idx < 16 * 6 * 66; idx += 256) {
            const int c = idx / 396, rem = idx % 396, r = rem / 66, ccx = rem % 66;
            const int gy = y0 - 1 + r, gx = ccx - 1;
            float v = 0.f;
            if (gy >= 0 && gy < 64 && gx >= 0 && gx < 64)
                v = yin[(cc * 16 + c) * HW_ + gy * 64 + gx];
            xs[idx] = to_tf32f(v);
        }
        __syncthreads();

        for (int kc = 0; kc < 18; kc++) {
            const int k1 = kc * 8 + lt;
            const int k2 = k1 + 4;
            const int c1 = k1 / 9, r1 = k1 % 9, kh1 = r1 / 3, kw1 = r1 % 3;
            const int c2 = k2 / 9, r2 = k2 % 9, kh2 = r2 / 3, kw2 = r2 % 3;
            const int aA1 = c1 * 396 + (wm + kh1) * 66 + kw1 + lg;
            const int aA2 = c2 * 396 + (wm + kh2) * 66 + kw2 + lg;

            unsigned bfr[4][2];
            #pragma unroll
            for (int n = 0; n < 4; n++) {
                const int oc = wn * 32 + n * 8 + lg;
                bfr[n][0] = __float_as_uint(ws[k1 * 72 + oc]);
                bfr[n][1] = __float_as_uint(ws[k2 * 72 + oc]);
            }
            #pragma unroll
            for (int m = 0; m < 4; m++) {
                const int xo = m * 16;
                const unsigned a0 = __float_as_uint(xs[aA1 + xo]);
                const unsigned a1 = __float_as_uint(xs[aA1 + xo + 8]);
                const unsigned a2 = __float_as_uint(xs[aA2 + xo]);
                const unsigned a3 = __float_as_uint(xs[aA2 + xo + 8]);
                #pragma unroll
                for (int n = 0; n < 4; n++)
                    mma_tf32(acc[m][n][0], acc[m][n][1], acc[m][n][2], acc[m][n][3],
                             a0, a1, a2, a3, bfr[n][0], bfr[n][1]);
            }
        }
    }

    const int y = y0 + wm;
    #pragma unroll
    for (int m = 0; m < 4; m++) {
        #pragma unroll
        for (int n = 0; n < 4; n++) {
            const int ocA = wn * 32 + n * 8 + 2 * lt;
            const int x0 = m * 16 + lg;
            #pragma unroll
            for (int r = 0; r < 4; r++) {
                const int oc = ocA + (r & 1);
                const int xx = x0 + ((r & 2) ? 8 : 0);
                out[((size_t)(bt * 64 + oc)) * 4096 + y * 64 + xx] = acc[m][n][r] + bs[oc];
            }
        }
    }
}

// ============================================================================
extern "C" void kernel_launch(void* const* d_in, const int* in_sizes, int n_in,
                              void* d_out, int out_size)
{
    const float* x  = (const float*)d_in[0];
    const float* wq = (const float*)d_in[1];
    const float* bq = (const float*)d_in[2];
    const float* wk = (const float*)d_in[3];
    const float* bk = (const float*)d_in[4];
    const float* wv = (const float*)d_in[5];
    const float* bv = (const float*)d_in[6];
    const float* wo = (const float*)d_in[7];
    const float* bo = (const float*)d_in[8];
    float* out = (float*)d_out;

    const int SM1 = (28800 + 4224 + 192) * 4;  // 132864
    const int SM2 = (8704 + 8704) * 4;         // 69632
    const int SM4 = (4096 + 8192) * 4;         // 49152
    const int SM5 = (10368 + 6336 + 64) * 4;   // 67072

    cudaFuncSetAttribute(k_qkv_tc,  cudaFuncAttributeMaxDynamicSharedMemorySize, SM1);
    cudaFuncSetAttribute(k_scores,  cudaFuncAttributeMaxDynamicSharedMemorySize, SM2);
    cudaFuncSetAttribute(k_av,      cudaFuncAttributeMaxDynamicSharedMemorySize, SM4);
    cudaFuncSetAttribute(k_convo_tc,cudaFuncAttributeMaxDynamicSharedMemorySize, SM5);

    k_qkv_tc  <<<dim3(32, 128), 256, SM1>>>(x, wq, bq, wk, bk, wv, bv);
    k_scores  <<<dim3(64, 16),  256, SM2>>>();
    k_softmax <<<dim3(64, 16),  64>>>();
    k_av      <<<dim3(256, 16), 256, SM4>>>();
    k_convo_tc<<<dim3(16, 128), 256, SM5>>>(wo, bo, out);
}

// round 4
// speedup vs baseline: 1.9355x; 1.0702x over previous
#include <cuda_runtime.h>
#include <math.h>

// Problem constants
#define B_    2
#define T_    64
#define BT_   128
#define CIN_  16
#define HW_   4096
#define OC_   64
#define NH_   8
#define DD_   32768
#define BH_   16
#define NCHUNK_ 32      // score d-chunks (d=1024 each)

// ---------------- scratch (device globals) -----------------------------------
__device__ float g_q[(size_t)BH_ * T_ * DD_];            // 128 MB
__device__ float g_k[(size_t)BH_ * T_ * DD_];            // 128 MB
__device__ float g_v[(size_t)BH_ * T_ * DD_];            // 128 MB
__device__ float g_Sp[(size_t)BH_ * NCHUNK_ * T_ * T_];  // 8.4 MB
__device__ float g_att[(size_t)BH_ * T_ * T_];           // 256 KB
__device__ float g_y[(size_t)BT_ * OC_ * HW_];           // 128 MB

__device__ __forceinline__ unsigned to_tf32(float x) {
    unsigned r;
    asm("cvt.rna.tf32.f32 %0, %1;" : "=r"(r) : "f"(x));
    return r;
}
__device__ __forceinline__ float to_tf32f(float x) {
    return __uint_as_float(to_tf32(x));
}

__device__ __forceinline__ void mma_tf32(float& d0, float& d1, float& d2, float& d3,
                                         unsigned a0, unsigned a1, unsigned a2, unsigned a3,
                                         unsigned b0, unsigned b1) {
    asm volatile(
        "mma.sync.aligned.m16n8k8.row.col.f32.tf32.tf32.f32 "
        "{%0,%1,%2,%3},{%4,%5,%6,%7},{%8,%9},{%0,%1,%2,%3};"
        : "+f"(d0), "+f"(d1), "+f"(d2), "+f"(d3)
        : "r"(a0), "r"(a1), "r"(a2), "r"(a3), "r"(b0), "r"(b1));
}

// ============================================================================
// Kernel 1: fused QKV 3x3 conv via TF32 tensor cores.
// Block: loops over 8 y-pairs; weights staged ONCE per block.
// 8 warps: wm = warp&1 (image row of pair), wn = warp>>1 (oc group of 48).
// Warp tile M=64, N=48, K=144.  grid (4, 128).
// ============================================================================
__global__ __launch_bounds__(256) void k_qkv_tc(
    const float* __restrict__ x,
    const float* __restrict__ wq, const float* __restrict__ bq,
    const float* __restrict__ wk, const float* __restrict__ bk,
    const float* __restrict__ wv, const float* __restrict__ bv)
{
    extern __shared__ float sm[];
    float* ws = sm;                  // 144*200 = 28800
    float* xs = sm + 28800;          // 16*4*66 = 4224
    float* bs = xs + 4224;           // 192

    const int tid = threadIdx.x;
    const int bt  = blockIdx.y;
    const float* xin = x + (size_t)bt * CIN_ * HW_;

    // stage weights once: ws[k][oc] (stride 200), tf32
    for (int idx = tid; idx < 192 * 144; idx += 256) {
        const int oc = idx / 144, k = idx % 144;
        const float* wsrc = (oc < 64) ? wq : ((oc < 128) ? wk : wv);
        ws[k * 200 + oc] = to_tf32f(wsrc[(oc & 63) * 144 + k]);
    }
    if (tid < 192) bs[tid] = (tid < 64) ? bq[tid] : ((tid < 128) ? bk[tid - 64] : bv[tid - 128]);

    const int warp = tid >> 5, lane = tid & 31;
    const int wm = warp & 1, wn = warp >> 1;
    const int lg = lane >> 2, lt = lane & 3;
    const int b = bt >> 6, t = bt & 63;

    for (int yi = 0; yi < 8; yi++) {
        const int y0 = (blockIdx.x * 8 + yi) * 2;   // 0..62
        __syncthreads();   // prior iter's xs reads done / weights visible
        for (int idx = tid; idx < 16 * 4 * 66; idx += 256) {
            const int c = idx / 264, rem = idx % 264, r = rem / 66, cc = rem % 66;
            const int gy = y0 - 1 + r, gx = cc - 1;
            float v = 0.f;
            if (gy >= 0 && gy < 64 && gx >= 0 && gx < 64) v = xin[c * HW_ + gy * 64 + gx];
            xs[idx] = to_tf32f(v);
        }
        __syncthreads();

        float acc[4][6][4];
        #pragma unroll
        for (int m = 0; m < 4; m++)
            #pragma unroll
            for (int n = 0; n < 6; n++)
                #pragma unroll
                for (int r = 0; r < 4; r++) acc[m][n][r] = 0.f;

        for (int kc = 0; kc < 18; kc++) {
            const int k1 = kc * 8 + lt;
            const int k2 = k1 + 4;
            const int c1 = k1 / 9, r1 = k1 % 9, kh1 = r1 / 3, kw1 = r1 % 3;
            const int c2 = k2 / 9, r2 = k2 % 9, kh2 = r2 / 3, kw2 = r2 % 3;
            const int aA1 = c1 * 264 + (wm + kh1) * 66 + kw1 + lg;
            const int aA2 = c2 * 264 + (wm + kh2) * 66 + kw2 + lg;

            unsigned bfr[6][2];
            #pragma unroll
            for (int n = 0; n < 6; n++) {
                const int oc = wn * 48 + n * 8 + lg;
                bfr[n][0] = __float_as_uint(ws[k1 * 200 + oc]);
                bfr[n][1] = __float_as_uint(ws[k2 * 200 + oc]);
            }
            #pragma unroll
            for (int m = 0; m < 4; m++) {
                const int xo = m * 16;
                const unsigned a0 = __float_as_uint(xs[aA1 + xo]);
                const unsigned a1 = __float_as_uint(xs[aA1 + xo + 8]);
                const unsigned a2 = __float_as_uint(xs[aA2 + xo]);
                const unsigned a3 = __float_as_uint(xs[aA2 + xo + 8]);
                #pragma unroll
                for (int n = 0; n < 6; n++)
                    mma_tf32(acc[m][n][0], acc[m][n][1], acc[m][n][2], acc[m][n][3],
                             a0, a1, a2, a3, bfr[n][0], bfr[n][1]);
            }
        }

        const int y = y0 + wm;
        #pragma unroll
        for (int m = 0; m < 4; m++) {
            #pragma unroll
            for (int n = 0; n < 6; n++) {
                const int ocA = wn * 48 + n * 8 + 2 * lt;
                const int x0 = m * 16 + lg;
                #pragma unroll
                for (int r = 0; r < 4; r++) {
                    const int oc = ocA + (r & 1);
                    const int xx = x0 + ((r & 2) ? 8 : 0);
                    float* dst = (oc < 64) ? g_q : ((oc < 128) ? g_k : g_v);
                    const int ol = oc & 63;
                    const size_t addr = ((size_t)((b * 8 + (ol >> 3)) * 64 + t)) * DD_
                                      + (size_t)(ol & 7) * 4096 + y * 64 + xx;
                    dst[addr] = acc[m][n][r] + bs[oc];
                }
            }
        }
    }
}

// ============================================================================
// Kernel 2: partial scores via TF32 mma. Sp[bh][chunk][64][64], d-chunk 1024.
// grid (32, 16), 256 threads. Warp tile M=32, N=16, K per substage = 128.
// smem: qs[64][132] natural (A), ks[128][72] transposed (B). Both
// fragment-load conflict-free (132 -> 4lg+lt, 72 -> 8lt+lg).
// ============================================================================
__global__ __launch_bounds__(256) void k_scores_tc()
{
    extern __shared__ float sm[];
    float* qs = sm;            // 64*132 = 8448
    float* ks = sm + 8448;     // 128*72 = 9216

    const int tid   = threadIdx.x;
    const int chunk = blockIdx.x;   // 0..31
    const int bh    = blockIdx.y;
    const int warp = tid >> 5, lane = tid & 31;
    const int wm = warp & 1, wn = warp >> 1;        // wn 0..3
    const int lg = lane >> 2, lt = lane & 3;

    float acc[2][2][4];
    #pragma unroll
    for (int m = 0; m < 2; m++)
        #pragma unroll
        for (int n = 0; n < 2; n++)
            #pragma unroll
            for (int r = 0; r < 4; r++) acc[m][n][r] = 0.f;

    for (int sub = 0; sub < 8; sub++) {
        const int d0 = chunk * 1024 + sub * 128;
        __syncthreads();
        for (int idx = tid; idx < 8192; idx += 256) {
            const int row = idx >> 7, dd = idx & 127;
            const size_t g = ((size_t)(bh * T_ + row)) * DD_ + d0 + dd;
            qs[row * 132 + dd] = to_tf32f(g_q[g]);
            ks[dd * 72 + row]  = to_tf32f(g_k[g]);
        }
        __syncthreads();

        #pragma unroll
        for (int ks8 = 0; ks8 < 16; ks8++) {
            const int k1 = ks8 * 8 + lt;
            unsigned bfr[2][2];
            #pragma unroll
            for (int n = 0; n < 2; n++) {
                const int n0 = wn * 16 + n * 8 + lg;
                bfr[n][0] = __float_as_uint(ks[k1 * 72 + n0]);
                bfr[n][1] = __float_as_uint(ks[(k1 + 4) * 72 + n0]);
            }
            #pragma unroll
            for (int m = 0; m < 2; m++) {
                const int m0 = wm * 32 + m * 16 + lg;
                const unsigned a0 = __float_as_uint(qs[m0 * 132 + k1]);
                const unsigned a1 = __float_as_uint(qs[(m0 + 8) * 132 + k1]);
                const unsigned a2 = __float_as_uint(qs[m0 * 132 + k1 + 4]);
                const unsigned a3 = __float_as_uint(qs[(m0 + 8) * 132 + k1 + 4]);
                #pragma unroll
                for (int n = 0; n < 2; n++)
                    mma_tf32(acc[m][n][0], acc[m][n][1], acc[m][n][2], acc[m][n][3],
                             a0, a1, a2, a3, bfr[n][0], bfr[n][1]);
            }
        }
    }

    float* Sp = &g_Sp[(size_t)(bh * NCHUNK_ + chunk) * 4096];
    #pragma unroll
    for (int m = 0; m < 2; m++) {
        #pragma unroll
        for (int n = 0; n < 2; n++) {
            const int row = wm * 32 + m * 16 + lg;
            const int col = wn * 16 + n * 8 + 2 * lt;
            *(float2*)&Sp[row * 64 + col]       = make_float2(acc[m][n][0], acc[m][n][1]);
            *(float2*)&Sp[(row + 8) * 64 + col] = make_float2(acc[m][n][2], acc[m][n][3]);
        }
    }
}

// ============================================================================
// Kernel 3: reduce 32 partials + causal softmax. grid (64 t, 16 bh), 64 thr.
// ============================================================================
__global__ void k_softmax()
{
    const int t = blockIdx.x, bh = blockIdx.y, k = threadIdx.x;
    __shared__ float red[64];
    float s = 0.f;
    #pragma unroll 8
    for (int ch = 0; ch < NCHUNK_; ch++)
        s += g_Sp[((size_t)(bh * NCHUNK_ + ch) * T_ + t) * T_ + k];
    s *= 0.005524271728019903f;   // 1/sqrt(32768)
    const bool valid = (k <= t);
    red[k] = valid ? s : -3.0e38f;
    __syncthreads();
    for (int off = 32; off; off >>= 1) {
        if (k < off) red[k] = fmaxf(red[k], red[k + off]);
        __syncthreads();
    }
    const float m = red[0];
    __syncthreads();
    const float e = valid ? expf(s - m) : 0.f;
    red[k] = e;
    __syncthreads();
    for (int off = 32; off; off >>= 1) {
        if (k < off) red[k] += red[k + off];
        __syncthreads();
    }
    g_att[((size_t)bh * T_ + t) * T_ + k] = e / red[0];
}

// ============================================================================
// Kernel 4: y = att * V via TF32 mma -> conv layout g_y[bt][oc][px].
// grid (256 d-tiles of 128, 16 bh), 256 threads.
// Warp tile M=32 (t), N=32 (d), K=64. smem: att[64][68], vs[64][136],
// both fragment-conflict-free (68 -> 4lg+lt, 136 -> 8lt+lg).
// ============================================================================
__global__ __launch_bounds__(256) void k_av_tc()
{
    extern __shared__ float sm[];
    float* as = sm;            // 64*68 = 4352
    float* vs = sm + 4352;     // 64*136 = 8704

    const int tid = threadIdx.x;
    const int dt  = blockIdx.x;
    const int bh  = blockIdx.y;
    const int d0  = dt * 128;

    for (int idx = tid; idx < 4096; idx += 256) {
        const int t = idx >> 6, k = idx & 63;
        as[t * 68 + k] = to_tf32f(g_att[(size_t)bh * 4096 + idx]);
    }
    for (int idx = tid; idx < 8192; idx += 256) {
        const int k = idx >> 7, dd = idx & 127;
        vs[k * 136 + dd] = to_tf32f(g_v[((size_t)(bh * T_ + k)) * DD_ + d0 + dd]);
    }
    __syncthreads();

    const int warp = tid >> 5, lane = tid & 31;
    const int wm = warp & 1, wn = warp >> 1;        // wn 0..3 (d group of 32)
    const int lg = lane >> 2, lt = lane & 3;

    float acc[2][4][4];
    #pragma unroll
    for (int m = 0; m < 2; m++)
        #pragma unroll
        for (int n = 0; n < 4; n++)
            #pragma unroll
            for (int r = 0; r < 4; r++) acc[m][n][r] = 0.f;

    #pragma unroll
    for (int ks8 = 0; ks8 < 8; ks8++) {
        const int k1 = ks8 * 8 + lt;
        unsigned bfr[4][2];
        #pragma unroll
        for (int n = 0; n < 4; n++) {
            const int n0 = wn * 32 + n * 8 + lg;
            bfr[n][0] = __float_as_uint(vs[k1 * 136 + n0]);
            bfr[n][1] = __float_as_uint(vs[(k1 + 4) * 136 + n0]);
        }
        #pragma unroll
        for (int m = 0; m < 2; m++) {
            const int m0 = wm * 32 + m * 16 + lg;
            const unsigned a0 = __float_as_uint(as[m0 * 68 + k1]);
            const unsigned a1 = __float_as_uint(as[(m0 + 8) * 68 + k1]);
            const unsigned a2 = __float_as_uint(as[m0 * 68 + k1 + 4]);
            const unsigned a3 = __float_as_uint(as[(m0 + 8) * 68 + k1 + 4]);
            #pragma unroll
            for (int n = 0; n < 4; n++)
                mma_tf32(acc[m][n][0], acc[m][n][1], acc[m][n][2], acc[m][n][3],
                         a0, a1, a2, a3, bfr[n][0], bfr[n][1]);
        }
    }

    const int h = bh & 7, b = bh >> 3;
    const int hc  = d0 >> 12;
    const int px0 = d0 & 4095;
    const int oc  = h * 8 + hc;
    #pragma unroll
    for (int m = 0; m < 2; m++) {
        #pragma unroll
        for (int n = 0; n < 4; n++) {
            const int row = wm * 32 + m * 16 + lg;
            const int dcol = wn * 32 + n * 8 + 2 * lt;
            {
                const int bt = b * 64 + row;
                float* dst = &g_y[((size_t)(bt * 64 + oc)) * 4096 + px0 + dcol];
                *(float2*)dst = make_float2(acc[m][n][0], acc[m][n][1]);
            }
            {
                const int bt = b * 64 + row + 8;
                float* dst = &g_y[((size_t)(bt * 64 + oc)) * 4096 + px0 + dcol];
                *(float2*)dst = make_float2(acc[m][n][2], acc[m][n][3]);
            }
        }
    }
}

// ============================================================================
// Kernel 5: output 3x3 conv (64 -> 64) via TF32 tensor cores.
// Full weight panel ws[576][72] (166 KB) staged ONCE per block; block loops
// over 4 y-tiles (16 rows).  grid (4, 128). 8 warps: wm = warp&3 (row),
// wn = warp>>2 (oc group of 32). Warp tile M=64, N=32.
// ============================================================================
__global__ __launch_bounds__(256) void k_convo_tc(
    const float* __restrict__ wo, const float* __restrict__ bo, float* __restrict__ out)
{
    extern __shared__ float sm[];
    float* ws = sm;                  // 576*72 = 41472
    float* xs = sm + 41472;          // 16*6*66 = 6336
    float* bs = xs + 6336;           // 64

    const int tid = threadIdx.x;
    const int bt  = blockIdx.y;
    const float* yin = g_y + (size_t)bt * OC_ * HW_;

    // stage full weight panel once: ws[k][oc], stride 72 (banks 8lt+lg: clean)
    for (int idx = tid; idx < 64 * 576; idx += 256) {
        const int oc = idx / 576, k = idx % 576;
        ws[k * 72 + oc] = to_tf32f(wo[(size_t)oc * 576 + k]);
    }
    if (tid < 64) bs[tid] = bo[tid];

    const int warp = tid >> 5, lane = tid & 31;
    const int wm = warp & 3, wn = warp >> 2;
    const int lg = lane >> 2, lt = lane & 3;

    for (int yt = 0; yt < 4; yt++) {
        const int y0 = blockIdx.x * 16 + yt * 4;    // 0..60

        float acc[4][4][4];
        #pragma unroll
        for (int m = 0; m < 4; m++)
            #pragma unroll
            for (int n = 0; n < 4; n++)
                #pragma unroll
                for (int r = 0; r < 4; r++) acc[m][n][r] = 0.f;

        for (int cc = 0; cc < 4; cc++) {
            __syncthreads();
            for (int idx = tid; idx < 16 * 6 * 66; idx += 256) {
                const int c = idx / 396, rem = idx % 396, r = rem / 66, ccx = rem % 66;
                const int gy = y0 - 1 + r, gx = ccx - 1;
                float v = 0.f;
                if (gy >= 0 && gy < 64 && gx >= 0 && gx < 64)
                    v = yin[(cc * 16 + c) * HW_ + gy * 64 + gx];
                xs[idx] = to_tf32f(v);
            }
            __syncthreads();

            for (int kc = 0; kc < 18; kc++) {
                const int k1 = kc * 8 + lt;
                const int k2 = k1 + 4;
                const int c1 = k1 / 9, r1 = k1 % 9, kh1 = r1 / 3, kw1 = r1 % 3;
                const int c2 = k2 / 9, r2 = k2 % 9, kh2 = r2 / 3, kw2 = r2 % 3;
                const int aA1 = c1 * 396 + (wm + kh1) * 66 + kw1 + lg;
                const int aA2 = c2 * 396 + (wm + kh2) * 66 + kw2 + lg;
                const int kg1 = cc * 144 + k1, kg2 = cc * 144 + k2;

                unsigned bfr[4][2];
                #pragma unroll
                for (int n = 0; n < 4; n++) {
                    const int oc = wn * 32 + n * 8 + lg;
                    bfr[n][0] = __float_as_uint(ws[kg1 * 72 + oc]);
                    bfr[n][1] = __float_as_uint(ws[kg2 * 72 + oc]);
                }
                #pragma unroll
                for (int m = 0; m < 4; m++) {
                    const int xo = m * 16;
                    const unsigned a0 = __float_as_uint(xs[aA1 + xo]);
                    const unsigned a1 = __float_as_uint(xs[aA1 + xo + 8]);
                    const unsigned a2 = __float_as_uint(xs[aA2 + xo]);
                    const unsigned a3 = __float_as_uint(xs[aA2 + xo + 8]);
                    #pragma unroll
                    for (int n = 0; n < 4; n++)
                        mma_tf32(acc[m][n][0], acc[m][n][1], acc[m][n][2], acc[m][n][3],
                                 a0, a1, a2, a3, bfr[n][0], bfr[n][1]);
                }
            }
        }

        const int y = y0 + wm;
        #pragma unroll
        for (int m = 0; m < 4; m++) {
            #pragma unroll
            for (int n = 0; n < 4; n++) {
                const int ocA = wn * 32 + n * 8 + 2 * lt;
                const int x0 = m * 16 + lg;
                #pragma unroll
                for (int r = 0; r < 4; r++) {
                    const int oc = ocA + (r & 1);
                    const int xx = x0 + ((r & 2) ? 8 : 0);
                    out[((size_t)(bt * 64 + oc)) * 4096 + y * 64 + xx] = acc[m][n][r] + bs[oc];
                }
            }
        }
    }
}

// ============================================================================
extern "C" void kernel_launch(void* const* d_in, const int* in_sizes, int n_in,
                              void* d_out, int out_size)
{
    const float* x  = (const float*)d_in[0];
    const float* wq = (const float*)d_in[1];
    const float* bq = (const float*)d_in[2];
    const float* wk = (const float*)d_in[3];
    const float* bk = (const float*)d_in[4];
    const float* wv = (const float*)d_in[5];
    const float* bv = (const float*)d_in[6];
    const float* wo = (const float*)d_in[7];
    const float* bo = (const float*)d_in[8];
    float* out = (float*)d_out;

    const int SM1 = (28800 + 4224 + 192) * 4;   // 132864
    const int SM2 = (8448 + 9216) * 4;          // 70656
    const int SM4 = (4352 + 8704) * 4;          // 52224
    const int SM5 = (41472 + 6336 + 64) * 4;    // 191488

    cudaFuncSetAttribute(k_qkv_tc,   cudaFuncAttributeMaxDynamicSharedMemorySize, SM1);
    cudaFuncSetAttribute(k_scores_tc,cudaFuncAttributeMaxDynamicSharedMemorySize, SM2);
    cudaFuncSetAttribute(k_av_tc,    cudaFuncAttributeMaxDynamicSharedMemorySize, SM4);
    cudaFuncSetAttribute(k_convo_tc, cudaFuncAttributeMaxDynamicSharedMemorySize, SM5);

    k_qkv_tc   <<<dim3(4, 128),        256, SM1>>>(x, wq, bq, wk, bk, wv, bv);
    k_scores_tc<<<dim3(NCHUNK_, 16),   256, SM2>>>();
    k_softmax  <<<dim3(64, 16),        64>>>();
    k_av_tc    <<<dim3(256, 16),       256, SM4>>>();
    k_convo_tc <<<dim3(4, 128),        256, SM5>>>(wo, bo, out);
}

// round 7
// speedup vs baseline: 2.9198x; 1.5086x over previous
#include <cuda_runtime.h>
#include <math.h>

// Problem constants
#define B_    2
#define T_    64
#define BT_   128
#define CIN_  16
#define HW_   4096
#define OC_   64
#define NH_   8
#define DD_   32768
#define BH_   16
#define NCHUNK_ 32      // score d-chunks (d=1024 each)

// ---------------- scratch (device globals) -----------------------------------
__device__ float g_q[(size_t)BH_ * T_ * DD_];            // 128 MB
__device__ float g_k[(size_t)BH_ * T_ * DD_];            // 128 MB
__device__ float g_v[(size_t)BH_ * T_ * DD_];            // 128 MB
__device__ float g_Sp[(size_t)BH_ * NCHUNK_ * T_ * T_];  // 8.4 MB
__device__ float g_att[(size_t)BH_ * T_ * T_];           // 256 KB
__device__ float g_y[(size_t)BT_ * OC_ * HW_];           // 128 MB

__device__ __forceinline__ unsigned to_tf32(float x) {
    unsigned r;
    asm("cvt.rna.tf32.f32 %0, %1;" : "=r"(r) : "f"(x));
    return r;
}
__device__ __forceinline__ float to_tf32f(float x) {
    return __uint_as_float(to_tf32(x));
}

__device__ __forceinline__ void mma_tf32(float& d0, float& d1, float& d2, float& d3,
                                         unsigned a0, unsigned a1, unsigned a2, unsigned a3,
                                         unsigned b0, unsigned b1) {
    asm volatile(
        "mma.sync.aligned.m16n8k8.row.col.f32.tf32.tf32.f32 "
        "{%0,%1,%2,%3},{%4,%5,%6,%7},{%8,%9},{%0,%1,%2,%3};"
        : "+f"(d0), "+f"(d1), "+f"(d2), "+f"(d3)
        : "r"(a0), "r"(a1), "r"(a2), "r"(a3), "r"(b0), "r"(b1));
}

// ============================================================================
// Kernel 1: fused QKV 3x3 conv via TF32 tensor cores.
// grid (4 y-groups, 128 bt, 2 oc-halves). Each block: 96 oc half-panel
// ws[144][104] (stride 104 >= 96, == 8 mod 32 -> frag banks 8lt+lg clean).
// smem 75.4 KB -> 2 blocks/SM. Block loops 8 y-pairs; weights staged once.
// 8 warps: wm = warp&1 (image row), wn = warp>>1 (oc group of 24).
// ============================================================================
#define WSTR_ 104
__global__ __launch_bounds__(256, 2) void k_qkv_tc(
    const float* __restrict__ x,
    const float* __restrict__ wq, const float* __restrict__ bq,
    const float* __restrict__ wk, const float* __restrict__ bk,
    const float* __restrict__ wv, const float* __restrict__ bv)
{
    extern __shared__ float sm[];
    float* ws = sm;                  // 144*104 = 14976
    float* xs = sm + 14976;          // 16*4*66 = 4224
    float* bs = xs + 4224;           // 96

    const int tid  = threadIdx.x;
    const int bt   = blockIdx.y;
    const int half = blockIdx.z;     // 0: oc 0..95, 1: oc 96..191
    const float* xin = x + (size_t)bt * CIN_ * HW_;

    // stage this half's weights once: ws[k][oc_l] (stride 104), tf32
    for (int idx = tid; idx < 96 * 144; idx += 256) {
        const int oc_l = idx / 144, k = idx % 144;
        const int ocg = half * 96 + oc_l;
        const float* wsrc = (ocg < 64) ? wq : ((ocg < 128) ? wk : wv);
        ws[k * WSTR_ + oc_l] = to_tf32f(wsrc[(ocg & 63) * 144 + k]);
    }
    if (tid < 96) {
        const int ocg = half * 96 + tid;
        bs[tid] = (ocg < 64) ? bq[ocg] : ((ocg < 128) ? bk[ocg - 64] : bv[ocg - 128]);
    }

    const int warp = tid >> 5, lane = tid & 31;
    const int wm = warp & 1, wn = warp >> 1;     // wn 0..3, 24 oc each
    const int lg = lane >> 2, lt = lane & 3;
    const int b = bt >> 6, t = bt & 63;

    for (int yi = 0; yi < 8; yi++) {
        const int y0 = (blockIdx.x * 8 + yi) * 2;   // 0..62
        __syncthreads();
        for (int idx = tid; idx < 16 * 4 * 66; idx += 256) {
            const int c = idx / 264, rem = idx % 264, r = rem / 66, cc = rem % 66;
            const int gy = y0 - 1 + r, gx = cc - 1;
            float v = 0.f;
            if (gy >= 0 && gy < 64 && gx >= 0 && gx < 64) v = xin[c * HW_ + gy * 64 + gx];
            xs[idx] = to_tf32f(v);
        }
        __syncthreads();

        float acc[4][3][4];
        #pragma unroll
        for (int m = 0; m < 4; m++)
            #pragma unroll
            for (int n = 0; n < 3; n++)
                #pragma unroll
                for (int r = 0; r < 4; r++) acc[m][n][r] = 0.f;

        for (int kc = 0; kc < 18; kc++) {
            const int k1 = kc * 8 + lt;
            const int k2 = k1 + 4;
            const int c1 = k1 / 9, r1 = k1 % 9, kh1 = r1 / 3, kw1 = r1 % 3;
            const int c2 = k2 / 9, r2 = k2 % 9, kh2 = r2 / 3, kw2 = r2 % 3;
            const int aA1 = c1 * 264 + (wm + kh1) * 66 + kw1 + lg;
            const int aA2 = c2 * 264 + (wm + kh2) * 66 + kw2 + lg;

            unsigned bfr[3][2];
            #pragma unroll
            for (int n = 0; n < 3; n++) {
                const int oc_l = wn * 24 + n * 8 + lg;
                bfr[n][0] = __float_as_uint(ws[k1 * WSTR_ + oc_l]);
                bfr[n][1] = __float_as_uint(ws[k2 * WSTR_ + oc_l]);
            }
            #pragma unroll
            for (int m = 0; m < 4; m++) {
                const int xo = m * 16;
                const unsigned a0 = __float_as_uint(xs[aA1 + xo]);
                const unsigned a1 = __float_as_uint(xs[aA1 + xo + 8]);
                const unsigned a2 = __float_as_uint(xs[aA2 + xo]);
                const unsigned a3 = __float_as_uint(xs[aA2 + xo + 8]);
                #pragma unroll
                for (int n = 0; n < 3; n++)
                    mma_tf32(acc[m][n][0], acc[m][n][1], acc[m][n][2], acc[m][n][3],
                             a0, a1, a2, a3, bfr[n][0], bfr[n][1]);
            }
        }

        const int y = y0 + wm;
        #pragma unroll
        for (int m = 0; m < 4; m++) {
            #pragma unroll
            for (int n = 0; n < 3; n++) {
                const int ocA = wn * 24 + n * 8 + 2 * lt;    // local oc
                const int x0 = m * 16 + lg;
                #pragma unroll
                for (int r = 0; r < 4; r++) {
                    const int oc_l = ocA + (r & 1);
                    const int ocg  = half * 96 + oc_l;
                    const int xx = x0 + ((r & 2) ? 8 : 0);
                    float* dst = (ocg < 64) ? g_q : ((ocg < 128) ? g_k : g_v);
                    const int ol = ocg & 63;
                    const size_t addr = ((size_t)((b * 8 + (ol >> 3)) * 64 + t)) * DD_
                                      + (size_t)(ol & 7) * 4096 + y * 64 + xx;
                    dst[addr] = acc[m][n][r] + bs[oc_l];
                }
            }
        }
    }
}

// ============================================================================
// Kernel 2: partial scores via TF32 mma. Sp[bh][chunk][64][64], d-chunk 1024.
// Both q and k staged NATURAL [row][dd] stride 132 -> float4 coalesced,
// conflict-free staging; frag reads banks 4lg+lt: clean.
// smem 67.6 KB -> 2 blocks/SM. grid (32, 16), 256 threads.
// ============================================================================
__global__ __launch_bounds__(256, 2) void k_scores_tc()
{
    extern __shared__ float sm[];
    float* qs = sm;            // 64*132 = 8448
    float* kn = sm + 8448;     // 64*132 = 8448

    const int tid   = threadIdx.x;
    const int chunk = blockIdx.x;   // 0..31
    const int bh    = blockIdx.y;
    const int warp = tid >> 5, lane = tid & 31;
    const int wm = warp & 1, wn = warp >> 1;        // wn 0..3
    const int lg = lane >> 2, lt = lane & 3;

    float acc[2][2][4];
    #pragma unroll
    for (int m = 0; m < 2; m++)
        #pragma unroll
        for (int n = 0; n < 2; n++)
            #pragma unroll
            for (int r = 0; r < 4; r++) acc[m][n][r] = 0.f;

    for (int sub = 0; sub < 8; sub++) {
        const int d0 = chunk * 1024 + sub * 128;
        __syncthreads();
        for (int i = tid; i < 2048; i += 256) {      // float4 granularity
            const int row = i >> 5, dd = (i & 31) << 2;
            const size_t g = ((size_t)(bh * T_ + row)) * DD_ + d0 + dd;
            const float4 q4 = *(const float4*)&g_q[g];
            const float4 k4 = *(const float4*)&g_k[g];
            *(float4*)&qs[row * 132 + dd] = make_float4(
                to_tf32f(q4.x), to_tf32f(q4.y), to_tf32f(q4.z), to_tf32f(q4.w));
            *(float4*)&kn[row * 132 + dd] = make_float4(
                to_tf32f(k4.x), to_tf32f(k4.y), to_tf32f(k4.z), to_tf32f(k4.w));
        }
        __syncthreads();

        #pragma unroll
        for (int ks8 = 0; ks8 < 16; ks8++) {
            const int k1 = ks8 * 8 + lt;
            unsigned bfr[2][2];
            #pragma unroll
            for (int n = 0; n < 2; n++) {
                const int n0 = wn * 16 + n * 8 + lg;
                bfr[n][0] = __float_as_uint(kn[n0 * 132 + k1]);
                bfr[n][1] = __float_as_uint(kn[n0 * 132 + k1 + 4]);
            }
            #pragma unroll
            for (int m = 0; m < 2; m++) {
                const int m0 = wm * 32 + m * 16 + lg;
                const unsigned a0 = __float_as_uint(qs[m0 * 132 + k1]);
                const unsigned a1 = __float_as_uint(qs[(m0 + 8) * 132 + k1]);
                const unsigned a2 = __float_as_uint(qs[m0 * 132 + k1 + 4]);
                const unsigned a3 = __float_as_uint(qs[(m0 + 8) * 132 + k1 + 4]);
                #pragma unroll
                for (int n = 0; n < 2; n++)
                    mma_tf32(acc[m][n][0], acc[m][n][1], acc[m][n][2], acc[m][n][3],
                             a0, a1, a2, a3, bfr[n][0], bfr[n][1]);
            }
        }
    }

    float* Sp = &g_Sp[(size_t)(bh * NCHUNK_ + chunk) * 4096];
    #pragma unroll
    for (int m = 0; m < 2; m++) {
        #pragma unroll
        for (int n = 0; n < 2; n++) {
            const int row = wm * 32 + m * 16 + lg;
            const int col = wn * 16 + n * 8 + 2 * lt;
            *(float2*)&Sp[row * 64 + col]       = make_float2(acc[m][n][0], acc[m][n][1]);
            *(float2*)&Sp[(row + 8) * 64 + col] = make_float2(acc[m][n][2], acc[m][n][3]);
        }
    }
}

// ============================================================================
// Kernel 3: reduce 32 partials + causal softmax. grid (64 t, 16 bh), 64 thr.
// ============================================================================
__global__ void k_softmax()
{
    const int t = blockIdx.x, bh = blockIdx.y, k = threadIdx.x;
    __shared__ float red[64];
    float s = 0.f;
    #pragma unroll 8
    for (int ch = 0; ch < NCHUNK_; ch++)
        s += g_Sp[((size_t)(bh * NCHUNK_ + ch) * T_ + t) * T_ + k];
    s *= 0.005524271728019903f;   // 1/sqrt(32768)
    const bool valid = (k <= t);
    red[k] = valid ? s : -3.0e38f;
    __syncthreads();
    for (int off = 32; off; off >>= 1) {
        if (k < off) red[k] = fmaxf(red[k], red[k + off]);
        __syncthreads();
    }
    const float m = red[0];
    __syncthreads();
    const float e = valid ? expf(s - m) : 0.f;
    red[k] = e;
    __syncthreads();
    for (int off = 32; off; off >>= 1) {
        if (k < off) red[k] += red[k + off];
        __syncthreads();
    }
    g_att[((size_t)bh * T_ + t) * T_ + k] = e / red[0];
}

// ============================================================================
// Kernel 4: y = att * V via TF32 mma -> conv layout g_y[bt][oc][px].
// float4 staging; 64-reg cap for 4 blocks/SM.
// grid (256 d-tiles of 128, 16 bh), 256 threads.
// ============================================================================
__global__ __launch_bounds__(256, 4) void k_av_tc()
{
    extern __shared__ float sm[];
    float* as = sm;            // 64*68 = 4352
    float* vs = sm + 4352;     // 64*136 = 8704

    const int tid = threadIdx.x;
    const int dt  = blockIdx.x;
    const int bh  = blockIdx.y;
    const int d0  = dt * 128;

    for (int i = tid; i < 1024; i += 256) {     // att: 1024 float4
        const int t = i >> 4, k = (i & 15) << 2;
        const float4 a4 = *(const float4*)&g_att[(size_t)bh * 4096 + t * 64 + k];
        *(float4*)&as[t * 68 + k] = make_float4(
            to_tf32f(a4.x), to_tf32f(a4.y), to_tf32f(a4.z), to_tf32f(a4.w));
    }
    for (int i = tid; i < 2048; i += 256) {     // v: 2048 float4
        const int k = i >> 5, dd = (i & 31) << 2;
        const float4 v4 = *(const float4*)&g_v[((size_t)(bh * T_ + k)) * DD_ + d0 + dd];
        *(float4*)&vs[k * 136 + dd] = make_float4(
            to_tf32f(v4.x), to_tf32f(v4.y), to_tf32f(v4.z), to_tf32f(v4.w));
    }
    __syncthreads();

    const int warp = tid >> 5, lane = tid & 31;
    const int wm = warp & 1, wn = warp >> 1;        // wn 0..3 (d group of 32)
    const int lg = lane >> 2, lt = lane & 3;

    float acc[2][4][4];
    #pragma unroll
    for (int m = 0; m < 2; m++)
        #pragma unroll
        for (int n = 0; n < 4; n++)
            #pragma unroll
            for (int r = 0; r < 4; r++) acc[m][n][r] = 0.f;

    #pragma unroll
    for (int ks8 = 0; ks8 < 8; ks8++) {
        const int k1 = ks8 * 8 + lt;
        unsigned bfr[4][2];
        #pragma unroll
        for (int n = 0; n < 4; n++) {
            const int n0 = wn * 32 + n * 8 + lg;
            bfr[n][0] = __float_as_uint(vs[k1 * 136 + n0]);
            bfr[n][1] = __float_as_uint(vs[(k1 + 4) * 136 + n0]);
        }
        #pragma unroll
        for (int m = 0; m < 2; m++) {
            const int m0 = wm * 32 + m * 16 + lg;
            const unsigned a0 = __float_as_uint(as[m0 * 68 + k1]);
            const unsigned a1 = __float_as_uint(as[(m0 + 8) * 68 + k1]);
            const unsigned a2 = __float_as_uint(as[m0 * 68 + k1 + 4]);
            const unsigned a3 = __float_as_uint(as[(m0 + 8) * 68 + k1 + 4]);
            #pragma unroll
            for (int n = 0; n < 4; n++)
                mma_tf32(acc[m][n][0], acc[m][n][1], acc[m][n][2], acc[m][n][3],
                         a0, a1, a2, a3, bfr[n][0], bfr[n][1]);
        }
    }

    const int h = bh & 7, b = bh >> 3;
    const int hc  = d0 >> 12;
    const int px0 = d0 & 4095;
    const int oc  = h * 8 + hc;
    #pragma unroll
    for (int m = 0; m < 2; m++) {
        #pragma unroll
        for (int n = 0; n < 4; n++) {
            const int row = wm * 32 + m * 16 + lg;
            const int dcol = wn * 32 + n * 8 + 2 * lt;
            {
                const int bt = b * 64 + row;
                float* dst = &g_y[((size_t)(bt * 64 + oc)) * 4096 + px0 + dcol];
                *(float2*)dst = make_float2(acc[m][n][0], acc[m][n][1]);
            }
            {
                const int bt = b * 64 + row + 8;
                float* dst = &g_y[((size_t)(bt * 64 + oc)) * 4096 + px0 + dcol];
                *(float2*)dst = make_float2(acc[m][n][2], acc[m][n][3]);
            }
        }
    }
}

// ============================================================================
// Kernel 5: output 3x3 conv (64 -> 64) via TF32 tensor cores.
// Full weight panel ws[576][72] staged once; xs DOUBLE-BUFFERED with register
// prefetch: next (yt,cc) tile's global loads overlap the current mma block.
// grid (4, 128). 8 warps: wm = warp&3 (row), wn = warp>>2 (oc group of 32).
// ============================================================================
#define NX_ (16 * 6 * 66)    // 6336
__global__ __launch_bounds__(256) void k_convo_tc(
    const float* __restrict__ wo, const float* __restrict__ bo, float* __restrict__ out)
{
    extern __shared__ float sm[];
    float* ws = sm;                  // 576*72 = 41472
    float* xs = sm + 41472;          // 2 * 6336 = 12672
    float* bs = xs + 2 * NX_;        // 64

    const int tid = threadIdx.x;
    const int bt  = blockIdx.y;
    const float* yin = g_y + (size_t)bt * OC_ * HW_;

    // stage full weight panel once: ws[k][oc], stride 72
    for (int idx = tid; idx < 64 * 576; idx += 256) {
        const int oc = idx / 576, k = idx % 576;
        ws[k * 72 + oc] = to_tf32f(wo[(size_t)oc * 576 + k]);
    }
    if (tid < 64) bs[tid] = bo[tid];

    const int warp = tid >> 5, lane = tid & 31;
    const int wm = warp & 3, wn = warp >> 2;
    const int lg = lane >> 2, lt = lane & 3;

    // initial stage: s = 0 (yt=0, cc=0) into buffer 0
    {
        const int y0 = blockIdx.x * 16;
        for (int idx = tid; idx < NX_; idx += 256) {
            const int c = idx / 396, rem = idx % 396, r = rem / 66, ccx = rem % 66;
            const int gy = y0 - 1 + r, gx = ccx - 1;
            float v = 0.f;
            if (gy >= 0 && gy < 64 && gx >= 0 && gx < 64)
                v = yin[c * HW_ + gy * 64 + gx];
            xs[idx] = to_tf32f(v);
        }
    }
    __syncthreads();

    float acc[4][4][4];

    for (int s = 0; s < 16; s++) {
        const int yt = s >> 2, cc = s & 3;
        const float* xcur = xs + (s & 1) * NX_;
        float*       xnxt = xs + ((s + 1) & 1) * NX_;

        // issue prefetch loads for stage s+1 (held in regs through the mma block)
        float pre[25];
        if (s < 15) {
            const int s2 = s + 1;
            const int yt2 = s2 >> 2, cc2 = s2 & 3;
            const int y0n = blockIdx.x * 16 + yt2 * 4;
            #pragma unroll
            for (int j = 0; j < 25; j++) {
                const int idx = tid + j * 256;
                float v = 0.f;
                if (idx < NX_) {
                    const int c = idx / 396, rem = idx % 396, r = rem / 66, ccx = rem % 66;
                    const int gy = y0n - 1 + r, gx = ccx - 1;
                    if (gy >= 0 && gy < 64 && gx >= 0 && gx < 64)
                        v = yin[(cc2 * 16 + c) * HW_ + gy * 64 + gx];
                }
                pre[j] = v;
            }
        }

        if (cc == 0) {
            #pragma unroll
            for (int m = 0; m < 4; m++)
                #pragma unroll
                for (int n = 0; n < 4; n++)
                    #pragma unroll
                    for (int r = 0; r < 4; r++) acc[m][n][r] = 0.f;
        }

        for (int kc = 0; kc < 18; kc++) {
            const int k1 = kc * 8 + lt;
            const int k2 = k1 + 4;
            const int c1 = k1 / 9, r1 = k1 % 9, kh1 = r1 / 3, kw1 = r1 % 3;
            const int c2 = k2 / 9, r2 = k2 % 9, kh2 = r2 / 3, kw2 = r2 % 3;
            const int aA1 = c1 * 396 + (wm + kh1) * 66 + kw1 + lg;
            const int aA2 = c2 * 396 + (wm + kh2) * 66 + kw2 + lg;
            const int kg1 = cc * 144 + k1, kg2 = cc * 144 + k2;

            unsigned bfr[4][2];
            #pragma unroll
            for (int n = 0; n < 4; n++) {
                const int oc = wn * 32 + n * 8 + lg;
                bfr[n][0] = __float_as_uint(ws[kg1 * 72 + oc]);
                bfr[n][1] = __float_as_uint(ws[kg2 * 72 + oc]);
            }
            #pragma unroll
            for (int m = 0; m < 4; m++) {
                const int xo = m * 16;
                const unsigned a0 = __float_as_uint(xcur[aA1 + xo]);
                const unsigned a1 = __float_as_uint(xcur[aA1 + xo + 8]);
                const unsigned a2 = __float_as_uint(xcur[aA2 + xo]);
                const unsigned a3 = __float_as_uint(xcur[aA2 + xo + 8]);
                #pragma unroll
                for (int n = 0; n < 4; n++)
                    mma_tf32(acc[m][n][0], acc[m][n][1], acc[m][n][2], acc[m][n][3],
                             a0, a1, a2, a3, bfr[n][0], bfr[n][1]);
            }
        }

        // commit prefetched tile to the other buffer
        if (s < 15) {
            #pragma unroll
            for (int j = 0; j < 25; j++) {
                const int idx = tid + j * 256;
                if (idx < NX_) xnxt[idx] = to_tf32f(pre[j]);
            }
        }
        __syncthreads();

        if (cc == 3) {
            const int y = blockIdx.x * 16 + yt * 4 + wm;
            #pragma unroll
            for (int m = 0; m < 4; m++) {
                #pragma unroll
                for (int n = 0; n < 4; n++) {
                    const int ocA = wn * 32 + n * 8 + 2 * lt;
                    const int x0 = m * 16 + lg;
                    #pragma unroll
                    for (int r = 0; r < 4; r++) {
                        const int oc = ocA + (r & 1);
                        const int xx = x0 + ((r & 2) ? 8 : 0);
                        out[((size_t)(bt * 64 + oc)) * 4096 + y * 64 + xx] = acc[m][n][r] + bs[oc];
                    }
                }
            }
        }
    }
}

// ============================================================================
extern "C" void kernel_launch(void* const* d_in, const int* in_sizes, int n_in,
                              void* d_out, int out_size)
{
    const float* x  = (const float*)d_in[0];
    const float* wq = (const float*)d_in[1];
    const float* bq = (const float*)d_in[2];
    const float* wk = (const float*)d_in[3];
    const float* bk = (const float*)d_in[4];
    const float* wv = (const float*)d_in[5];
    const float* bv = (const float*)d_in[6];
    const float* wo = (const float*)d_in[7];
    const float* bo = (const float*)d_in[8];
    float* out = (float*)d_out;

    const int SM1 = (14976 + 4224 + 96) * 4;        // 77184  -> 2 blocks/SM
    const int SM2 = (8448 + 8448) * 4;              // 67584  -> 2 blocks/SM
    const int SM4 = (4352 + 8704) * 4;              // 52224  -> 4 blocks/SM
    const int SM5 = (41472 + 2 * NX_ + 64) * 4;     // 216832 -> 1 block/SM

    cudaFuncSetAttribute(k_qkv_tc,   cudaFuncAttributeMaxDynamicSharedMemorySize, SM1);
    cudaFuncSetAttribute(k_scores_tc,cudaFuncAttributeMaxDynamicSharedMemorySize, SM2);
    cudaFuncSetAttribute(k_av_tc,    cudaFuncAttributeMaxDynamicSharedMemorySize, SM4);
    cudaFuncSetAttribute(k_convo_tc, cudaFuncAttributeMaxDynamicSharedMemorySize, SM5);

    k_qkv_tc   <<<dim3(4, 128, 2),   256, SM1>>>(x, wq, bq, wk, bk, wv, bv);
    k_scores_tc<<<dim3(NCHUNK_, 16), 256, SM2>>>();
    k_softmax  <<<dim3(64, 16),      64>>>();
    k_av_tc    <<<dim3(256, 16),     256, SM4>>>();
    k_convo_tc <<<dim3(4, 128),      256, SM5>>>(wo, bo, out);
}

// round 8
// speedup vs baseline: 3.2629x; 1.1175x over previous
#include <cuda_runtime.h>
#include <math.h>

// Problem constants
#define B_    2
#define T_    64
#define BT_   128
#define CIN_  16
#define HW_   4096
#define OC_   64
#define NH_   8
#define DD_   32768
#define BH_   16
#define NCHUNK_ 32      // score d-chunks (d=1024 each)

// ---------------- scratch (device globals) -----------------------------------
__device__ float g_q[(size_t)BH_ * T_ * DD_];            // 128 MB
__device__ float g_k[(size_t)BH_ * T_ * DD_];            // 128 MB
__device__ float g_v[(size_t)BH_ * T_ * DD_];            // 128 MB
__device__ float g_Sp[(size_t)BH_ * NCHUNK_ * T_ * T_];  // 8.4 MB
__device__ float g_att[(size_t)BH_ * T_ * T_];           // 256 KB
__device__ float g_y[(size_t)BT_ * OC_ * HW_];           // 128 MB

__device__ __forceinline__ unsigned to_tf32(float x) {
    unsigned r;
    asm("cvt.rna.tf32.f32 %0, %1;" : "=r"(r) : "f"(x));
    return r;
}
__device__ __forceinline__ float to_tf32f(float x) {
    return __uint_as_float(to_tf32(x));
}

__device__ __forceinline__ void mma_tf32(float& d0, float& d1, float& d2, float& d3,
                                         unsigned a0, unsigned a1, unsigned a2, unsigned a3,
                                         unsigned b0, unsigned b1) {
    asm volatile(
        "mma.sync.aligned.m16n8k8.row.col.f32.tf32.tf32.f32 "
        "{%0,%1,%2,%3},{%4,%5,%6,%7},{%8,%9},{%0,%1,%2,%3};"
        : "+f"(d0), "+f"(d1), "+f"(d2), "+f"(d3)
        : "r"(a0), "r"(a1), "r"(a2), "r"(a3), "r"(b0), "r"(b1));
}

// K-dimension ordering for conv GEMMs: k = r*16 + c  (r = 3x3 tap, c = channel)
// -> c = k & 15, r = k >> 4, kh = r/3 = (r*11)>>5 (exact for r<9), kw = r - 3*kh.

// ============================================================================
// Kernel 1: fused QKV 3x3 conv via TF32 tensor cores.
// grid (4 y-groups, 128 bt, 2 oc-halves). Each block: 96 oc half-panel
// ws[144][104]; smem 75.4 KB -> 2 blocks/SM. Loops 8 y-pairs.
// 8 warps: wm = warp&1 (image row), wn = warp>>1 (oc group of 24).
// ============================================================================
#define WSTR_ 104
__global__ __launch_bounds__(256, 2) void k_qkv_tc(
    const float* __restrict__ x,
    const float* __restrict__ wq, const float* __restrict__ bq,
    const float* __restrict__ wk, const float* __restrict__ bk,
    const float* __restrict__ wv, const float* __restrict__ bv)
{
    extern __shared__ float sm[];
    float* ws = sm;                  // 144*104 = 14976
    float* xs = sm + 14976;          // 16*4*66 = 4224
    float* bs = xs + 4224;           // 96

    const int tid  = threadIdx.x;
    const int bt   = blockIdx.y;
    const int half = blockIdx.z;     // 0: oc 0..95, 1: oc 96..191
    const float* xin = x + (size_t)bt * CIN_ * HW_;

    // stage this half's weights once, K-reordered: ws[r*16+c][oc_l]
    for (int idx = tid; idx < 96 * 144; idx += 256) {
        const int oc_l = idx / 144, k = idx % 144;
        const int r = k >> 4, c = k & 15;
        const int ocg = half * 96 + oc_l;
        const float* wsrc = (ocg < 64) ? wq : ((ocg < 128) ? wk : wv);
        ws[k * WSTR_ + oc_l] = to_tf32f(wsrc[(ocg & 63) * 144 + c * 9 + r]);
    }
    if (tid < 96) {
        const int ocg = half * 96 + tid;
        bs[tid] = (ocg < 64) ? bq[ocg] : ((ocg < 128) ? bk[ocg - 64] : bv[ocg - 128]);
    }

    const int warp = tid >> 5, lane = tid & 31;
    const int wm = warp & 1, wn = warp >> 1;     // wn 0..3, 24 oc each
    const int lg = lane >> 2, lt = lane & 3;
    const int b = bt >> 6, t = bt & 63;

    for (int yi = 0; yi < 8; yi++) {
        const int y0 = (blockIdx.x * 8 + yi) * 2;   // 0..62
        __syncthreads();
        for (int idx = tid; idx < 16 * 4 * 66; idx += 256) {
            const int c = idx / 264, rem = idx % 264, r = rem / 66, cc = rem % 66;
            const int gy = y0 - 1 + r, gx = cc - 1;
            float v = 0.f;
            if (gy >= 0 && gy < 64 && gx >= 0 && gx < 64) v = xin[c * HW_ + gy * 64 + gx];
            xs[idx] = to_tf32f(v);
        }
        __syncthreads();

        float acc[4][3][4];
        #pragma unroll
        for (int m = 0; m < 4; m++)
            #pragma unroll
            for (int n = 0; n < 3; n++)
                #pragma unroll
                for (int r = 0; r < 4; r++) acc[m][n][r] = 0.f;

        #pragma unroll
        for (int kc = 0; kc < 18; kc++) {
            const int k1 = kc * 8 + lt;
            const int k2 = k1 + 4;
            const int c1 = k1 & 15, r1 = k1 >> 4;
            const int c2 = k2 & 15, r2 = k2 >> 4;
            const int t1 = (r1 * 11) >> 5;         // r1/3
            const int t2 = (r2 * 11) >> 5;
            const int aA1 = c1 * 264 + (wm + t1) * 66 + (r1 - 3 * t1) + lg;
            const int aA2 = c2 * 264 + (wm + t2) * 66 + (r2 - 3 * t2) + lg;

            unsigned bfr[3][2];
            #pragma unroll
            for (int n = 0; n < 3; n++) {
                const int oc_l = wn * 24 + n * 8 + lg;
                bfr[n][0] = __float_as_uint(ws[k1 * WSTR_ + oc_l]);
                bfr[n][1] = __float_as_uint(ws[k2 * WSTR_ + oc_l]);
            }
            #pragma unroll
            for (int m = 0; m < 4; m++) {
                const int xo = m * 16;
                const unsigned a0 = __float_as_uint(xs[aA1 + xo]);
                const unsigned a1 = __float_as_uint(xs[aA1 + xo + 8]);
                const unsigned a2 = __float_as_uint(xs[aA2 + xo]);
                const unsigned a3 = __float_as_uint(xs[aA2 + xo + 8]);
                #pragma unroll
                for (int n = 0; n < 3; n++)
                    mma_tf32(acc[m][n][0], acc[m][n][1], acc[m][n][2], acc[m][n][3],
                             a0, a1, a2, a3, bfr[n][0], bfr[n][1]);
            }
        }

        const int y = y0 + wm;
        #pragma unroll
        for (int m = 0; m < 4; m++) {
            #pragma unroll
            for (int n = 0; n < 3; n++) {
                const int ocA = wn * 24 + n * 8 + 2 * lt;    // local oc
                const int x0 = m * 16 + lg;
                #pragma unroll
                for (int r = 0; r < 4; r++) {
                    const int oc_l = ocA + (r & 1);
                    const int ocg  = half * 96 + oc_l;
                    const int xx = x0 + ((r & 2) ? 8 : 0);
                    float* dst = (ocg < 64) ? g_q : ((ocg < 128) ? g_k : g_v);
                    const int ol = ocg & 63;
                    const size_t addr = ((size_t)((b * 8 + (ol >> 3)) * 64 + t)) * DD_
                                      + (size_t)(ol & 7) * 4096 + y * 64 + xx;
                    dst[addr] = acc[m][n][r] + bs[oc_l];
                }
            }
        }
    }
}

// ============================================================================
// Kernel 2: partial scores via TF32 mma. Sp[bh][chunk][64][64], d-chunk 1024.
// Natural [row][dd] stride-132 staging, float4 coalesced, conflict-free.
// smem 67.6 KB -> 2 blocks/SM. grid (32, 16), 256 threads.
// ============================================================================
__global__ __launch_bounds__(256, 2) void k_scores_tc()
{
    extern __shared__ float sm[];
    float* qs = sm;            // 64*132 = 8448
    float* kn = sm + 8448;     // 64*132 = 8448

    const int tid   = threadIdx.x;
    const int chunk = blockIdx.x;   // 0..31
    const int bh    = blockIdx.y;
    const int warp = tid >> 5, lane = tid & 31;
    const int wm = warp & 1, wn = warp >> 1;        // wn 0..3
    const int lg = lane >> 2, lt = lane & 3;

    float acc[2][2][4];
    #pragma unroll
    for (int m = 0; m < 2; m++)
        #pragma unroll
        for (int n = 0; n < 2; n++)
            #pragma unroll
            for (int r = 0; r < 4; r++) acc[m][n][r] = 0.f;

    for (int sub = 0; sub < 8; sub++) {
        const int d0 = chunk * 1024 + sub * 128;
        __syncthreads();
        for (int i = tid; i < 2048; i += 256) {      // float4 granularity
            const int row = i >> 5, dd = (i & 31) << 2;
            const size_t g = ((size_t)(bh * T_ + row)) * DD_ + d0 + dd;
            const float4 q4 = *(const float4*)&g_q[g];
            const float4 k4 = *(const float4*)&g_k[g];
            *(float4*)&qs[row * 132 + dd] = make_float4(
                to_tf32f(q4.x), to_tf32f(q4.y), to_tf32f(q4.z), to_tf32f(q4.w));
            *(float4*)&kn[row * 132 + dd] = make_float4(
                to_tf32f(k4.x), to_tf32f(k4.y), to_tf32f(k4.z), to_tf32f(k4.w));
        }
        __syncthreads();

        #pragma unroll
        for (int ks8 = 0; ks8 < 16; ks8++) {
            const int k1 = ks8 * 8 + lt;
            unsigned bfr[2][2];
            #pragma unroll
            for (int n = 0; n < 2; n++) {
                const int n0 = wn * 16 + n * 8 + lg;
                bfr[n][0] = __float_as_uint(kn[n0 * 132 + k1]);
                bfr[n][1] = __float_as_uint(kn[n0 * 132 + k1 + 4]);
            }
            #pragma unroll
            for (int m = 0; m < 2; m++) {
                const int m0 = wm * 32 + m * 16 + lg;
                const unsigned a0 = __float_as_uint(qs[m0 * 132 + k1]);
                const unsigned a1 = __float_as_uint(qs[(m0 + 8) * 132 + k1]);
                const unsigned a2 = __float_as_uint(qs[m0 * 132 + k1 + 4]);
                const unsigned a3 = __float_as_uint(qs[(m0 + 8) * 132 + k1 + 4]);
                #pragma unroll
                for (int n = 0; n < 2; n++)
                    mma_tf32(acc[m][n][0], acc[m][n][1], acc[m][n][2], acc[m][n][3],
                             a0, a1, a2, a3, bfr[n][0], bfr[n][1]);
            }
        }
    }

    float* Sp = &g_Sp[(size_t)(bh * NCHUNK_ + chunk) * 4096];
    #pragma unroll
    for (int m = 0; m < 2; m++) {
        #pragma unroll
        for (int n = 0; n < 2; n++) {
            const int row = wm * 32 + m * 16 + lg;
            const int col = wn * 16 + n * 8 + 2 * lt;
            *(float2*)&Sp[row * 64 + col]       = make_float2(acc[m][n][0], acc[m][n][1]);
            *(float2*)&Sp[(row + 8) * 64 + col] = make_float2(acc[m][n][2], acc[m][n][3]);
        }
    }
}

// ============================================================================
// Kernel 3: reduce 32 partials + causal softmax. grid (64 t, 16 bh), 64 thr.
// ============================================================================
__global__ void k_softmax()
{
    const int t = blockIdx.x, bh = blockIdx.y, k = threadIdx.x;
    __shared__ float red[64];
    float s = 0.f;
    #pragma unroll 8
    for (int ch = 0; ch < NCHUNK_; ch++)
        s += g_Sp[((size_t)(bh * NCHUNK_ + ch) * T_ + t) * T_ + k];
    s *= 0.005524271728019903f;   // 1/sqrt(32768)
    const bool valid = (k <= t);
    red[k] = valid ? s : -3.0e38f;
    __syncthreads();
    for (int off = 32; off; off >>= 1) {
        if (k < off) red[k] = fmaxf(red[k], red[k + off]);
        __syncthreads();
    }
    const float m = red[0];
    __syncthreads();
    const float e = valid ? expf(s - m) : 0.f;
    red[k] = e;
    __syncthreads();
    for (int off = 32; off; off >>= 1) {
        if (k < off) red[k] += red[k + off];
        __syncthreads();
    }
    g_att[((size_t)bh * T_ + t) * T_ + k] = e / red[0];
}

// ============================================================================
// Kernel 4: y = att * V via TF32 mma -> conv layout g_y[bt][oc][px].
// float4 staging; 64-reg cap for 4 blocks/SM.
// grid (256 d-tiles of 128, 16 bh), 256 threads.
// ============================================================================
__global__ __launch_bounds__(256, 4) void k_av_tc()
{
    extern __shared__ float sm[];
    float* as = sm;            // 64*68 = 4352
    float* vs = sm + 4352;     // 64*136 = 8704

    const int tid = threadIdx.x;
    const int dt  = blockIdx.x;
    const int bh  = blockIdx.y;
    const int d0  = dt * 128;

    for (int i = tid; i < 1024; i += 256) {     // att: 1024 float4
        const int t = i >> 4, k = (i & 15) << 2;
        const float4 a4 = *(const float4*)&g_att[(size_t)bh * 4096 + t * 64 + k];
        *(float4*)&as[t * 68 + k] = make_float4(
            to_tf32f(a4.x), to_tf32f(a4.y), to_tf32f(a4.z), to_tf32f(a4.w));
    }
    for (int i = tid; i < 2048; i += 256) {     // v: 2048 float4
        const int k = i >> 5, dd = (i & 31) << 2;
        const float4 v4 = *(const float4*)&g_v[((size_t)(bh * T_ + k)) * DD_ + d0 + dd];
        *(float4*)&vs[k * 136 + dd] = make_float4(
            to_tf32f(v4.x), to_tf32f(v4.y), to_tf32f(v4.z), to_tf32f(v4.w));
    }
    __syncthreads();

    const int warp = tid >> 5, lane = tid & 31;
    const int wm = warp & 1, wn = warp >> 1;        // wn 0..3 (d group of 32)
    const int lg = lane >> 2, lt = lane & 3;

    float acc[2][4][4];
    #pragma unroll
    for (int m = 0; m < 2; m++)
        #pragma unroll
        for (int n = 0; n < 4; n++)
            #pragma unroll
            for (int r = 0; r < 4; r++) acc[m][n][r] = 0.f;

    #pragma unroll
    for (int ks8 = 0; ks8 < 8; ks8++) {
        const int k1 = ks8 * 8 + lt;
        unsigned bfr[4][2];
        #pragma unroll
        for (int n = 0; n < 4; n++) {
            const int n0 = wn * 32 + n * 8 + lg;
            bfr[n][0] = __float_as_uint(vs[k1 * 136 + n0]);
            bfr[n][1] = __float_as_uint(vs[(k1 + 4) * 136 + n0]);
        }
        #pragma unroll
        for (int m = 0; m < 2; m++) {
            const int m0 = wm * 32 + m * 16 + lg;
            const unsigned a0 = __float_as_uint(as[m0 * 68 + k1]);
            const unsigned a1 = __float_as_uint(as[(m0 + 8) * 68 + k1]);
            const unsigned a2 = __float_as_uint(as[m0 * 68 + k1 + 4]);
            const unsigned a3 = __float_as_uint(as[(m0 + 8) * 68 + k1 + 4]);
            #pragma unroll
            for (int n = 0; n < 4; n++)
                mma_tf32(acc[m][n][0], acc[m][n][1], acc[m][n][2], acc[m][n][3],
                         a0, a1, a2, a3, bfr[n][0], bfr[n][1]);
        }
    }

    const int h = bh & 7, b = bh >> 3;
    const int hc  = d0 >> 12;
    const int px0 = d0 & 4095;
    const int oc  = h * 8 + hc;
    #pragma unroll
    for (int m = 0; m < 2; m++) {
        #pragma unroll
        for (int n = 0; n < 4; n++) {
            const int row = wm * 32 + m * 16 + lg;
            const int dcol = wn * 32 + n * 8 + 2 * lt;
            {
                const int bt = b * 64 + row;
                float* dst = &g_y[((size_t)(bt * 64 + oc)) * 4096 + px0 + dcol];
                *(float2*)dst = make_float2(acc[m][n][0], acc[m][n][1]);
            }
            {
                const int bt = b * 64 + row + 8;
                float* dst = &g_y[((size_t)(bt * 64 + oc)) * 4096 + px0 + dcol];
                *(float2*)dst = make_float2(acc[m][n][2], acc[m][n][3]);
            }
        }
    }
}

// ============================================================================
// Kernel 5: output 3x3 conv (64 -> 64) via TF32 tensor cores.
// Full weight panel ws[576][72] (K-reordered per 144-chunk) staged once;
// xs double-buffered with register prefetch. grid (4, 128).
// 8 warps: wm = warp&3 (row), wn = warp>>2 (oc group of 32).
// ============================================================================
#define NX_ (16 * 6 * 66)    // 6336
__global__ __launch_bounds__(256) void k_convo_tc(
    const float* __restrict__ wo, const float* __restrict__ bo, float* __restrict__ out)
{
    extern __shared__ float sm[];
    float* ws = sm;                  // 576*72 = 41472
    float* xs = sm + 41472;          // 2 * 6336 = 12672
    float* bs = xs + 2 * NX_;        // 64

    const int tid = threadIdx.x;
    const int bt  = blockIdx.y;
    const float* yin = g_y + (size_t)bt * OC_ * HW_;

    // stage full weight panel once, K-reordered within each 144-chunk:
    // kg = cc*144 + (r*16 + c_local), source channel = cc*16 + c_local
    for (int idx = tid; idx < 64 * 576; idx += 256) {
        const int oc = idx / 576, kg = idx % 576;
        const int cc = kg / 144, kl = kg % 144;
        const int r = kl >> 4, cl = kl & 15;
        ws[kg * 72 + oc] = to_tf32f(wo[(size_t)oc * 576 + (cc * 16 + cl) * 9 + r]);
    }
    if (tid < 64) bs[tid] = bo[tid];

    const int warp = tid >> 5, lane = tid & 31;
    const int wm = warp & 3, wn = warp >> 2;
    const int lg = lane >> 2, lt = lane & 3;

    // initial stage: s = 0 (yt=0, cc=0) into buffer 0
    {
        const int y0 = blockIdx.x * 16;
        for (int idx = tid; idx < NX_; idx += 256) {
            const int c = idx / 396, rem = idx % 396, r = rem / 66, ccx = rem % 66;
            const int gy = y0 - 1 + r, gx = ccx - 1;
            float v = 0.f;
            if (gy >= 0 && gy < 64 && gx >= 0 && gx < 64)
                v = yin[c * HW_ + gy * 64 + gx];
            xs[idx] = to_tf32f(v);
        }
    }
    __syncthreads();

    float acc[4][4][4];

    for (int s = 0; s < 16; s++) {
        const int yt = s >> 2, cc = s & 3;
        const float* xcur = xs + (s & 1) * NX_;
        float*       xnxt = xs + ((s + 1) & 1) * NX_;

        // issue prefetch loads for stage s+1 (held in regs through the mma block)
        float pre[25];
        if (s < 15) {
            const int s2 = s + 1;
            const int yt2 = s2 >> 2, cc2 = s2 & 3;
            const int y0n = blockIdx.x * 16 + yt2 * 4;
            #pragma unroll
            for (int j = 0; j < 25; j++) {
                const int idx = tid + j * 256;
                float v = 0.f;
                if (idx < NX_) {
                    const int c = idx / 396, rem = idx % 396, r = rem / 66, ccx = rem % 66;
                    const int gy = y0n - 1 + r, gx = ccx - 1;
                    if (gy >= 0 && gy < 64 && gx >= 0 && gx < 64)
                        v = yin[(cc2 * 16 + c) * HW_ + gy * 64 + gx];
                }
                pre[j] = v;
            }
        }

        if (cc == 0) {
            #pragma unroll
            for (int m = 0; m < 4; m++)
                #pragma unroll
                for (int n = 0; n < 4; n++)
                    #pragma unroll
                    for (int r = 0; r < 4; r++) acc[m][n][r] = 0.f;
        }

        #pragma unroll
        for (int kc = 0; kc < 18; kc++) {
            const int k1 = kc * 8 + lt;
            const int k2 = k1 + 4;
            const int c1 = k1 & 15, r1 = k1 >> 4;
            const int c2 = k2 & 15, r2 = k2 >> 4;
            const int t1 = (r1 * 11) >> 5;         // r1/3
            const int t2 = (r2 * 11) >> 5;
            const int aA1 = c1 * 396 + (wm + t1) * 66 + (r1 - 3 * t1) + lg;
            const int aA2 = c2 * 396 + (wm + t2) * 66 + (r2 - 3 * t2) + lg;
            const int kg1 = cc * 144 + k1, kg2 = cc * 144 + k2;

            unsigned bfr[4][2];
            #pragma unroll
            for (int n = 0; n < 4; n++) {
                const int oc = wn * 32 + n * 8 + lg;
                bfr[n][0] = __float_as_uint(ws[kg1 * 72 + oc]);
                bfr[n][1] = __float_as_uint(ws[kg2 * 72 + oc]);
            }
            #pragma unroll
            for (int m = 0; m < 4; m++) {
                const int xo = m * 16;
                const unsigned a0 = __float_as_uint(xcur[aA1 + xo]);
                const unsigned a1 = __float_as_uint(xcur[aA1 + xo + 8]);
                const unsigned a2 = __float_as_uint(xcur[aA2 + xo]);
                const unsigned a3 = __float_as_uint(xcur[aA2 + xo + 8]);
                #pragma unroll
                for (int n = 0; n < 4; n++)
                    mma_tf32(acc[m][n][0], acc[m][n][1], acc[m][n][2], acc[m][n][3],
                             a0, a1, a2, a3, bfr[n][0], bfr[n][1]);
            }
        }

        // commit prefetched tile to the other buffer
        if (s < 15) {
            #pragma unroll
            for (int j = 0; j < 25; j++) {
                const int idx = tid + j * 256;
                if (idx < NX_) xnxt[idx] = to_tf32f(pre[j]);
            }
        }
        __syncthreads();

        if (cc == 3) {
            const int y = blockIdx.x * 16 + yt * 4 + wm;
            #pragma unroll
            for (int m = 0; m < 4; m++) {
                #pragma unroll
                for (int n = 0; n < 4; n++) {
                    const int ocA = wn * 32 + n * 8 + 2 * lt;
                    const int x0 = m * 16 + lg;
                    #pragma unroll
                    for (int r = 0; r < 4; r++) {
                        const int oc = ocA + (r & 1);
                        const int xx = x0 + ((r & 2) ? 8 : 0);
                        out[((size_t)(bt * 64 + oc)) * 4096 + y * 64 + xx] = acc[m][n][r] + bs[oc];
                    }
                }
            }
        }
    }
}

// ============================================================================
extern "C" void kernel_launch(void* const* d_in, const int* in_sizes, int n_in,
                              void* d_out, int out_size)
{
    const float* x  = (const float*)d_in[0];
    const float* wq = (const float*)d_in[1];
    const float* bq = (const float*)d_in[2];
    const float* wk = (const float*)d_in[3];
    const float* bk = (const float*)d_in[4];
    const float* wv = (const float*)d_in[5];
    const float* bv = (const float*)d_in[6];
    const float* wo = (const float*)d_in[7];
    const float* bo = (const float*)d_in[8];
    float* out = (float*)d_out;

    const int SM1 = (14976 + 4224 + 96) * 4;        // 77184  -> 2 blocks/SM
    const int SM2 = (8448 + 8448) * 4;              // 67584  -> 2 blocks/SM
    const int SM4 = (4352 + 8704) * 4;              // 52224  -> 4 blocks/SM
    const int SM5 = (41472 + 2 * NX_ + 64) * 4;     // 216832 -> 1 block/SM

    cudaFuncSetAttribute(k_qkv_tc,   cudaFuncAttributeMaxDynamicSharedMemorySize, SM1);
    cudaFuncSetAttribute(k_scores_tc,cudaFuncAttributeMaxDynamicSharedMemorySize, SM2);
    cudaFuncSetAttribute(k_av_tc,    cudaFuncAttributeMaxDynamicSharedMemorySize, SM4);
    cudaFuncSetAttribute(k_convo_tc, cudaFuncAttributeMaxDynamicSharedMemorySize, SM5);

    k_qkv_tc   <<<dim3(4, 128, 2),   256, SM1>>>(x, wq, bq, wk, bk, wv, bv);
    k_scores_tc<<<dim3(NCHUNK_, 16), 256, SM2>>>();
    k_softmax  <<<dim3(64, 16),      64>>>();
    k_av_tc    <<<dim3(256, 16),     256, SM4>>>();
    k_convo_tc <<<dim3(4, 128),      256, SM5>>>(wo, bo, out);
}